// round 7
// baseline (speedup 1.0000x reference)
#include <cuda_runtime.h>
#include <cuda_bf16.h>
#include <cstdint>
#include <cmath>

// ---------------- problem sizes ----------------
#define T_STEPS 256
#define BATCH   64
#define KDIM    1024
#define NGATE   4096
#define HSTEP   ((size_t)BATCH * KDIM)     // 65536
#define ZSTEP   ((size_t)BATCH * NGATE)    // 262144

typedef __nv_bfloat16 bf16;

// ---------------- scratch globals ----------------
__device__ float g_Z0[(size_t)T_STEPS * BATCH * NGATE];     // layer-0 x-projection (+b0)
__device__ bf16  g_Xhi[(size_t)T_STEPS * BATCH * KDIM];
__device__ bf16  g_Xlo[(size_t)T_STEPS * BATCH * KDIM];
__device__ bf16  g_H1hi[(size_t)T_STEPS * BATCH * KDIM];    // layer-0 h planes
__device__ bf16  g_H1lo[(size_t)T_STEPS * BATCH * KDIM];
__device__ bf16  g_H2hi[(size_t)T_STEPS * BATCH * KDIM];    // layer-1 h planes
__device__ bf16  g_H2lo[(size_t)T_STEPS * BATCH * KDIM];
__device__ bf16  g_hz[2][BATCH * KDIM];                     // never written: zeros
__device__ float g_c0[BATCH * KDIM];
__device__ float g_c1[BATCH * KDIM];
// packed step weights (fragment order, 16-col CTAs): L0 K=1024, L1 K=2048 (x+h concat)
__device__ bf16  g_Ws0[2][(size_t)KDIM * NGATE];
__device__ bf16  g_Ws1[2][(size_t)2 * KDIM * NGATE];
// packed pre-GEMM weights for Z0
__device__ bf16  g_Wg0[2][(size_t)KDIM * NGATE];

#define DEVFN __device__ __forceinline__

// ---------------- mma / cp.async helpers ----------------
DEVFN void mma16(float* c, const uint32_t* a, uint2 b) {
    asm volatile(
        "mma.sync.aligned.m16n8k16.row.col.f32.bf16.bf16.f32 "
        "{%0,%1,%2,%3},{%4,%5,%6,%7},{%8,%9},{%0,%1,%2,%3};"
        : "+f"(c[0]), "+f"(c[1]), "+f"(c[2]), "+f"(c[3])
        : "r"(a[0]), "r"(a[1]), "r"(a[2]), "r"(a[3]), "r"(b.x), "r"(b.y));
}
DEVFN void cp16(void* s, const void* g) {
    uint32_t sa = (uint32_t)__cvta_generic_to_shared(s);
    asm volatile("cp.async.cg.shared.global [%0], [%1], 16;" :: "r"(sa), "l"(g));
}
DEVFN void cp_commit() { asm volatile("cp.async.commit_group;"); }
template <int N> DEVFN void cp_wait() { asm volatile("cp.async.wait_group %0;" :: "n"(N)); }

DEVFN void split_bf16(float w, bf16& hi, bf16& lo) {
    hi = __float2bfloat16(w);
    lo = __float2bfloat16(w - __bfloat162float(hi));
}

// ======================================================================
// Pack kernels (once per call)
// ======================================================================
// Step pack, 16-col CTAs. dst[(((cta*KB + kb)*8) + gt*2 + ng)*128 + lane*4 + reg*2 + hh]
__global__ void pack_stepW2(const float* __restrict__ W, int KB,
                            bf16* __restrict__ hi, bf16* __restrict__ lo)
{
    size_t idx = (size_t)blockIdx.x * blockDim.x + threadIdx.x;
    size_t total = (size_t)KB * 16 * NGATE;
    if (idx >= total) return;
    int k   = (int)(idx >> 12);
    int col = (int)(idx & 4095);
    int gt  = col >> 10, c = col & 1023;
    int cta = c >> 4, ccol = c & 15, ng = ccol >> 3, cc = ccol & 7;
    int kb  = k >> 4, kl = k & 15;
    int reg = kl >> 3, tg = (kl >> 1) & 3, hh = kl & 1;
    int lane = cc * 4 + tg;
    size_t dst = (((size_t)cta * KB + kb) * 8 + gt * 2 + ng) * 128 + lane * 4 + reg * 2 + hh;
    bf16 h, l; split_bf16(W[idx], h, l);
    hi[dst] = h; lo[dst] = l;
}

// Pre-GEMM pack: dst[(n8*64 + kb)*128 + lane*4 + reg*2 + hh]
__global__ void pack_gemmW(const float* __restrict__ W, bf16* __restrict__ hi,
                           bf16* __restrict__ lo)
{
    size_t idx = (size_t)blockIdx.x * blockDim.x + threadIdx.x;
    if (idx >= (size_t)KDIM * NGATE) return;
    int k   = (int)(idx >> 12);
    int col = (int)(idx & 4095);
    int n8  = col >> 3, cc = col & 7;
    int kb  = k >> 4,   kl = k & 15;
    int reg = kl >> 3, tg = (kl >> 1) & 3, hh = kl & 1;
    int lane = cc * 4 + tg;
    size_t dst = ((size_t)n8 * 64 + kb) * 128 + lane * 4 + reg * 2 + hh;
    bf16 h, l; split_bf16(W[idx], h, l);
    hi[dst] = h; lo[dst] = l;
}

__global__ void split_planes(const float* __restrict__ A, bf16* __restrict__ hi,
                             bf16* __restrict__ lo, size_t n)
{
    size_t idx = (size_t)blockIdx.x * blockDim.x + threadIdx.x;
    if (idx >= n) return;
    bf16 h, l; split_bf16(A[idx], h, l);
    hi[idx] = h; lo[idx] = l;
}

// ======================================================================
// bf16 3-term pre-GEMM for Z0
// ======================================================================
#define GA_STRIDE 40
#define G_SA_BYTES 40960
#define G_SMEM (G_SA_BYTES + 32768)

__global__ __launch_bounds__(256) void gemm_bf16(
    const bf16* __restrict__ Ahi, const bf16* __restrict__ Alo,
    const bf16* __restrict__ Bhi, const bf16* __restrict__ Blo,
    const float* __restrict__ bias, float* __restrict__ C)
{
    extern __shared__ char smem[];
    bf16* sA = (bf16*)smem;
    bf16* sB = (bf16*)(smem + G_SA_BYTES);

    const int tid  = threadIdx.x;
    const int warp = tid >> 5, lane = tid & 31;
    const int g  = lane >> 2, t4 = lane & 3;
    const int wm = warp >> 1, wn = warp & 1;
    const int m0 = blockIdx.y * 128;
    const int n0 = blockIdx.x * 128;
    const int n8base = n0 >> 3;

    float acc[2][8][4];
    #pragma unroll
    for (int i = 0; i < 2; i++)
        #pragma unroll
        for (int j = 0; j < 8; j++)
            #pragma unroll
            for (int k = 0; k < 4; k++) acc[i][j][k] = 0.f;

    auto issue = [&](int ks, int s) {
        #pragma unroll
        for (int p = 0; p < 4; p++) {
            int id = p * 256 + tid;
            int plane = id >> 9, rem = id & 511;
            int row = rem >> 2, c8 = rem & 3;
            const bf16* src = (plane ? Alo : Ahi)
                + (size_t)(m0 + row) * KDIM + ks * 32 + c8 * 8;
            cp16(&sA[((size_t)(s * 2 + plane) * 128 + row) * GA_STRIDE + c8 * 8], src);
        }
        #pragma unroll
        for (int p = 0; p < 4; p++) {
            int id = p * 256 + tid;
            int plane = id >> 9, rem = id & 511;
            int n8l = rem >> 5, r32 = rem & 31;
            const bf16* src = (plane ? Blo : Bhi)
                + ((size_t)(n8base + n8l) * 64 + ks * 2) * 128 + r32 * 8;
            cp16(&sB[((size_t)(s * 2 + plane) * 16 + n8l) * 256 + r32 * 8], src);
        }
    };

    issue(0, 0); cp_commit();

    for (int ks = 0; ks < KDIM / 32; ks++) {
        cp_wait<0>();
        __syncthreads();
        if (ks + 1 < KDIM / 32) issue(ks + 1, (ks + 1) & 1);
        cp_commit();
        const int s = ks & 1;

        #pragma unroll
        for (int kk = 0; kk < 2; kk++) {
            const int kloc = kk * 16 + t4 * 2;
            uint32_t ah[2][4], al[2][4];
            #pragma unroll
            for (int mf = 0; mf < 2; mf++) {
                int m = wm * 32 + mf * 16 + g;
                const bf16* p0 = &sA[((size_t)(s * 2) * 128 + m) * GA_STRIDE];
                const bf16* p1 = &sA[((size_t)(s * 2 + 1) * 128 + m) * GA_STRIDE];
                ah[mf][0] = *(const uint32_t*)(p0 + kloc);
                ah[mf][1] = *(const uint32_t*)(p0 + 8 * GA_STRIDE + kloc);
                ah[mf][2] = *(const uint32_t*)(p0 + kloc + 8);
                ah[mf][3] = *(const uint32_t*)(p0 + 8 * GA_STRIDE + kloc + 8);
                al[mf][0] = *(const uint32_t*)(p1 + kloc);
                al[mf][1] = *(const uint32_t*)(p1 + 8 * GA_STRIDE + kloc);
                al[mf][2] = *(const uint32_t*)(p1 + kloc + 8);
                al[mf][3] = *(const uint32_t*)(p1 + 8 * GA_STRIDE + kloc + 8);
            }
            #pragma unroll
            for (int nf = 0; nf < 8; nf++) {
                size_t base = ((size_t)(s * 2) * 16 + wn * 8 + nf) * 256 + kk * 128 + lane * 4;
                uint2 bhi = *(const uint2*)&sB[base];
                uint2 blo = *(const uint2*)&sB[base + 16 * 256];
                #pragma unroll
                for (int mf = 0; mf < 2; mf++) {
                    mma16(acc[mf][nf], ah[mf], bhi);
                    mma16(acc[mf][nf], al[mf], bhi);
                    mma16(acc[mf][nf], ah[mf], blo);
                }
            }
        }
    }

    #pragma unroll
    for (int mf = 0; mf < 2; mf++) {
        #pragma unroll
        for (int nf = 0; nf < 8; nf++) {
            int col = n0 + (wn * 8 + nf) * 8 + 2 * t4;
            int r0  = m0 + wm * 32 + mf * 16 + g;
            float bv0 = bias[col], bv1 = bias[col + 1];
            C[(size_t)r0 * NGATE + col]           = acc[mf][nf][0] + bv0;
            C[(size_t)r0 * NGATE + col + 1]       = acc[mf][nf][1] + bv1;
            C[(size_t)(r0 + 8) * NGATE + col]     = acc[mf][nf][2] + bv0;
            C[(size_t)(r0 + 8) * NGATE + col + 1] = acc[mf][nf][3] + bv1;
        }
    }
}

// ======================================================================
// Combined step launch t (t = 0..256):
//   CTAs 0-63   : layer-0 step t     (K=1024 recurrence, Zx from g_Z0)
//   CTAs 64-127 : layer-1 step t-1   (K=2048: [h1[t-1]; h2[t-2]] @ W1full + b1)
// 256 thr = 8 warps (4 M-warps x 2 N-groups), CTA owns 16 h-cols.
// NOTE: all buffers that are written are plain (non-const, non-restrict) ptrs.
// ======================================================================
#define SH_STRIDE 72
#define SW_BYTES (3 * 2 * 32 * 128 * 2)                  // 49152
#define S_SMEM (SW_BYTES + 3 * 2 * 64 * SH_STRIDE * 2)   // + 55296 = 104448

__global__ __launch_bounds__(256, 1) void lstm_combined(
    int t,
    const float* __restrict__ Z0,
    const float* __restrict__ b1,
    bf16* H1hi, bf16* H1lo,          // read [t-1], write [t]   (layer 0)
    bf16* H2hi, bf16* H2lo,          // read [s-1], write [s]   (layer 1)
    const bf16* __restrict__ hz,
    float* c0buf, float* c1buf,
    const bf16* __restrict__ Ws0hi, const bf16* __restrict__ Ws0lo,
    const bf16* __restrict__ Ws1hi, const bf16* __restrict__ Ws1lo,
    float* out)
{
    const bool isL1 = blockIdx.x >= 64;
    if (!isL1 && t >= T_STEPS) return;
    if (isL1 && t == 0) return;
    const int s = t - 1;
    const int cta = blockIdx.x & 63;

    extern __shared__ char smem[];
    bf16* sW = (bf16*)smem;
    bf16* sH = (bf16*)(smem + SW_BYTES);

    const int tid  = threadIdx.x;
    const int warp = tid >> 5, lane = tid & 31;
    const int g    = lane >> 2, t4 = lane & 3;
    const int mw   = warp & 3, ng = warp >> 2;
    const int mrow = mw * 16 + g;
    const int n0   = cta * 16 + ng * 8;

    const int NT = isL1 ? 32 : 16;
    const bf16* Wphi; const bf16* Wplo; size_t ctaW;
    if (isL1) { Wphi = Ws1hi; Wplo = Ws1lo; ctaW = (size_t)cta * (128 * 8 * 128); }
    else      { Wphi = Ws0hi; Wplo = Ws0lo; ctaW = (size_t)cta * (64 * 8 * 128); }
    const bool first = isL1 ? (s == 0) : (t == 0);
    float* cbuf = isL1 ? c1buf : c0buf;

    // h read sources
    const bf16 *hA_hi, *hA_lo, *hB_hi, *hB_lo;
    if (isL1) {
        hA_hi = H1hi + (size_t)s * HSTEP;  hA_lo = H1lo + (size_t)s * HSTEP;
        hB_hi = (s == 0) ? hz : (H2hi + (size_t)(s - 1) * HSTEP);
        hB_lo = (s == 0) ? (hz + HSTEP) : (H2lo + (size_t)(s - 1) * HSTEP);
    } else {
        hA_hi = (t == 0) ? hz : (H1hi + (size_t)(t - 1) * HSTEP);
        hA_lo = (t == 0) ? (hz + HSTEP) : (H1lo + (size_t)(t - 1) * HSTEP);
        hB_hi = hA_hi; hB_lo = hA_lo;   // unused for L0
    }

    // early prefetch: z-term + old c
    float zr[4][4];
    if (isL1) {
        #pragma unroll
        for (int gt = 0; gt < 4; gt++) {
            float2 bv = __ldg((const float2*)(b1 + gt * 1024 + n0 + t4 * 2));
            zr[gt][0] = bv.x; zr[gt][1] = bv.y;
            zr[gt][2] = bv.x; zr[gt][3] = bv.y;
        }
    } else {
        const float* zp = Z0 + (size_t)t * ZSTEP;
        #pragma unroll
        for (int gt = 0; gt < 4; gt++)
            #pragma unroll
            for (int rr = 0; rr < 2; rr++) {
                float2 v = __ldg((const float2*)(zp + (size_t)(mrow + rr * 8) * NGATE
                                                 + gt * 1024 + n0 + t4 * 2));
                zr[gt][rr * 2] = v.x; zr[gt][rr * 2 + 1] = v.y;
            }
    }
    float cold[4] = {0.f, 0.f, 0.f, 0.f};
    if (!first) {
        #pragma unroll
        for (int rr = 0; rr < 2; rr++) {
            float2 cv = *(const float2*)(cbuf + (size_t)(mrow + rr * 8) * KDIM
                                         + n0 + t4 * 2);
            cold[rr * 2] = cv.x; cold[rr * 2 + 1] = cv.y;
        }
    }

    // pipelined K loop
    auto issue = [&](int tile, int st) {
        const bf16* hhi; const bf16* hlo; int koff;
        if (tile < 16) { hhi = hA_hi; hlo = hA_lo; koff = tile * 64; }
        else           { hhi = hB_hi; hlo = hB_lo; koff = (tile - 16) * 64; }
        #pragma unroll
        for (int q = 0; q < 4; q++) {
            int id = q * 256 + tid;
            int plane = id >> 9, rem = id & 511;
            int row = rem >> 3, c8 = rem & 7;
            const bf16* src = (plane ? hlo : hhi) + (size_t)row * KDIM + koff + c8 * 8;
            cp16(&sH[((size_t)(st * 2 + plane) * 64 + row) * SH_STRIDE + c8 * 8], src);
        }
        #pragma unroll
        for (int q = 0; q < 4; q++) {
            int id = q * 256 + tid;
            int plane = id >> 9, rem = id & 511;
            int kbfg = rem >> 4, e8 = rem & 15;
            const bf16* src = (plane ? Wplo : Wphi) + ctaW
                + ((size_t)tile * 32 + kbfg) * 128 + e8 * 8;
            cp16(&sW[((size_t)(st * 2 + plane) * 32 + kbfg) * 128 + e8 * 8], src);
        }
    };

    float acc[4][4] = {};

    issue(0, 0); cp_commit();
    issue(1, 1); cp_commit();

    for (int tile = 0; tile < NT; tile++) {
        cp_wait<1>();
        __syncthreads();
        if (tile + 2 < NT) issue(tile + 2, (tile + 2) % 3);
        cp_commit();
        const int st = tile % 3;
        const bf16* h0 = &sH[(size_t)(st * 2) * 64 * SH_STRIDE];
        const bf16* h1 = &sH[(size_t)(st * 2 + 1) * 64 * SH_STRIDE];
        const bf16* w0 = &sW[(size_t)(st * 2) * 32 * 128];

        #pragma unroll
        for (int kbl = 0; kbl < 4; kbl++) {
            const int kloc = kbl * 16 + t4 * 2;
            uint32_t ahi[4], alo[4];
            ahi[0] = *(const uint32_t*)(h0 + (size_t)mrow * SH_STRIDE + kloc);
            ahi[1] = *(const uint32_t*)(h0 + (size_t)(mrow + 8) * SH_STRIDE + kloc);
            ahi[2] = *(const uint32_t*)(h0 + (size_t)mrow * SH_STRIDE + kloc + 8);
            ahi[3] = *(const uint32_t*)(h0 + (size_t)(mrow + 8) * SH_STRIDE + kloc + 8);
            alo[0] = *(const uint32_t*)(h1 + (size_t)mrow * SH_STRIDE + kloc);
            alo[1] = *(const uint32_t*)(h1 + (size_t)(mrow + 8) * SH_STRIDE + kloc);
            alo[2] = *(const uint32_t*)(h1 + (size_t)mrow * SH_STRIDE + kloc + 8);
            alo[3] = *(const uint32_t*)(h1 + (size_t)(mrow + 8) * SH_STRIDE + kloc + 8);
            #pragma unroll
            for (int gt = 0; gt < 4; gt++) {
                const bf16* wb = w0 + (size_t)(kbl * 8 + gt * 2 + ng) * 128 + lane * 4;
                uint2 bhi = *(const uint2*)wb;
                uint2 blo = *(const uint2*)(wb + 32 * 128);
                mma16(acc[gt], ahi, bhi);
                mma16(acc[gt], alo, bhi);
                mma16(acc[gt], ahi, blo);
            }
        }
    }

    // epilogue
    float hv[4], cn_[4];
    #pragma unroll
    for (int e = 0; e < 4; e++) {
        float zi = acc[0][e] + zr[0][e];
        float zj = acc[1][e] + zr[1][e];
        float zf = acc[2][e] + zr[2][e];
        float zo = acc[3][e] + zr[3][e];
        float ig = 1.f / (1.f + expf(-zi));
        float fg = 1.f / (1.f + expf(-(zf + 1.f)));   // FORGET_BIAS = 1.0
        float og = 1.f / (1.f + expf(-zo));
        float cn = cold[e] * fg + ig * tanhf(zj);
        cn_[e] = cn;
        hv[e] = tanhf(cn) * og;
    }

    #pragma unroll
    for (int rr = 0; rr < 2; rr++) {
        int r   = mrow + rr * 8;
        int col = n0 + t4 * 2;
        float h0v = hv[rr * 2], h1v = hv[rr * 2 + 1];
        bf16 h0h, h0l, h1h, h1l;
        split_bf16(h0v, h0h, h0l);
        split_bf16(h1v, h1h, h1l);
        *(float2*)&cbuf[(size_t)r * KDIM + col] = make_float2(cn_[rr * 2], cn_[rr * 2 + 1]);
        if (isL1) {
            *(float2*)&out[(size_t)s * HSTEP + (size_t)r * KDIM + col] = make_float2(h0v, h1v);
            *(__nv_bfloat162*)&H2hi[(size_t)s * HSTEP + (size_t)r * KDIM + col]
                = __halves2bfloat162(h0h, h1h);
            *(__nv_bfloat162*)&H2lo[(size_t)s * HSTEP + (size_t)r * KDIM + col]
                = __halves2bfloat162(h0l, h1l);
        } else {
            *(__nv_bfloat162*)&H1hi[(size_t)t * HSTEP + (size_t)r * KDIM + col]
                = __halves2bfloat162(h0h, h1h);
            *(__nv_bfloat162*)&H1lo[(size_t)t * HSTEP + (size_t)r * KDIM + col]
                = __halves2bfloat162(h0l, h1l);
        }
    }
}

// ======================================================================
extern "C" void kernel_launch(void* const* d_in, const int* in_sizes, int n_in,
                              void* d_out, int out_size)
{
    const float* X  = (const float*)d_in[0];
    const float* W0 = (const float*)d_in[1];
    const float* b0 = (const float*)d_in[2];
    const float* W1 = (const float*)d_in[3];
    const float* b1 = (const float*)d_in[4];
    float* out = (float*)d_out;

    float *Z0, *c0, *c1;
    bf16 *Xhi, *Xlo, *H1hi, *H1lo, *H2hi, *H2lo, *hz, *Ws0, *Ws1, *Wg0;
    cudaGetSymbolAddress((void**)&Z0,   g_Z0);
    cudaGetSymbolAddress((void**)&c0,   g_c0);
    cudaGetSymbolAddress((void**)&c1,   g_c1);
    cudaGetSymbolAddress((void**)&Xhi,  g_Xhi);
    cudaGetSymbolAddress((void**)&Xlo,  g_Xlo);
    cudaGetSymbolAddress((void**)&H1hi, g_H1hi);
    cudaGetSymbolAddress((void**)&H1lo, g_H1lo);
    cudaGetSymbolAddress((void**)&H2hi, g_H2hi);
    cudaGetSymbolAddress((void**)&H2lo, g_H2lo);
    cudaGetSymbolAddress((void**)&hz,   g_hz);
    cudaGetSymbolAddress((void**)&Ws0,  g_Ws0);
    cudaGetSymbolAddress((void**)&Ws1,  g_Ws1);
    cudaGetSymbolAddress((void**)&Wg0,  g_Wg0);

    const size_t WPLANE0 = (size_t)KDIM * NGATE;       // 4 M elems
    const size_t WPLANE1 = (size_t)2 * KDIM * NGATE;   // 8 M elems
    const size_t NX      = (size_t)T_STEPS * HSTEP;    // 16 M

    cudaFuncSetAttribute(gemm_bf16,     cudaFuncAttributeMaxDynamicSharedMemorySize, G_SMEM);
    cudaFuncSetAttribute(lstm_combined, cudaFuncAttributeMaxDynamicSharedMemorySize, S_SMEM);

    // ---- packs & splits ----
    const int pb = 256;
    pack_gemmW<<<(int)((WPLANE0 + pb - 1) / pb), pb>>>(W0, Wg0, Wg0 + WPLANE0);
    pack_stepW2<<<(int)((WPLANE0 + pb - 1) / pb), pb>>>(W0 + WPLANE0, 64,
                                                        Ws0, Ws0 + WPLANE0);
    pack_stepW2<<<(int)((WPLANE1 + pb - 1) / pb), pb>>>(W1, 128,
                                                        Ws1, Ws1 + WPLANE1);
    split_planes<<<(int)((NX + 255) / 256), 256>>>(X, Xhi, Xlo, NX);

    // ---- Z0 pre-GEMM ----
    gemm_bf16<<<dim3(NGATE / 128, (T_STEPS * BATCH) / 128), 256, G_SMEM>>>(
        Xhi, Xlo, Wg0, Wg0 + WPLANE0, b0, Z0);

    // ---- fused two-layer recurrence: 257 launches ----
    for (int t = 0; t <= T_STEPS; t++) {
        lstm_combined<<<128, 256, S_SMEM>>>(
            t, Z0, b1, H1hi, H1lo, H2hi, H2lo, hz, c0, c1,
            Ws0, Ws0 + WPLANE0, Ws1, Ws1 + WPLANE1, out);
    }
}

// round 11
// speedup vs baseline: 1.3698x; 1.3698x over previous
#include <cuda_runtime.h>
#include <cuda_fp16.h>
#include <cuda_bf16.h>
#include <cstdint>
#include <cmath>

#define T_STEPS 256
#define BATCH   64
#define KDIM    1024
#define NGATE   4096
#define HSTEP   ((size_t)BATCH * KDIM)
#define ZSTEP   ((size_t)BATCH * NGATE)

typedef __half f16;
typedef __nv_bfloat16 bf16;

// ---------------- scratch globals ----------------
__device__ float g_Z0[(size_t)T_STEPS * BATCH * NGATE];
__device__ bf16  g_Xhi[(size_t)T_STEPS * BATCH * KDIM];
__device__ bf16  g_Xlo[(size_t)T_STEPS * BATCH * KDIM];
__device__ bf16  g_Wg0[2][(size_t)KDIM * NGATE];
__device__ f16   g_H1[(size_t)T_STEPS * BATCH * KDIM];
__device__ f16   g_H2[(size_t)T_STEPS * BATCH * KDIM];
__device__ f16   g_hz[BATCH * KDIM];                    // never written: zeros
__device__ float g_c0[BATCH * KDIM];
__device__ float g_c1[BATCH * KDIM];
__device__ float g_z1x[2][BATCH * NGATE];               // ping-pong, b1 included
#define WPACK ((size_t)64 * 196608)                     // 12,582,912 halfs
__device__ f16   g_WpL0[WPACK];
__device__ f16   g_WpL1[WPACK];

#define DEVFN __device__ __forceinline__

DEVFN void mma16f(float* c, const uint32_t* a, uint2 b) {
    asm volatile("mma.sync.aligned.m16n8k16.row.col.f32.f16.f16.f32 "
        "{%0,%1,%2,%3},{%4,%5,%6,%7},{%8,%9},{%0,%1,%2,%3};"
        : "+f"(c[0]), "+f"(c[1]), "+f"(c[2]), "+f"(c[3])
        : "r"(a[0]), "r"(a[1]), "r"(a[2]), "r"(a[3]), "r"(b.x), "r"(b.y));
}
DEVFN void mma16b(float* c, const uint32_t* a, uint2 b) {
    asm volatile("mma.sync.aligned.m16n8k16.row.col.f32.bf16.bf16.f32 "
        "{%0,%1,%2,%3},{%4,%5,%6,%7},{%8,%9},{%0,%1,%2,%3};"
        : "+f"(c[0]), "+f"(c[1]), "+f"(c[2]), "+f"(c[3])
        : "r"(a[0]), "r"(a[1]), "r"(a[2]), "r"(a[3]), "r"(b.x), "r"(b.y));
}
DEVFN void cp16(void* s, const void* g) {
    uint32_t sa = (uint32_t)__cvta_generic_to_shared(s);
    asm volatile("cp.async.cg.shared.global [%0], [%1], 16;" :: "r"(sa), "l"(g));
}
DEVFN void cp_commit() { asm volatile("cp.async.commit_group;"); }
template <int N> DEVFN void cp_wait() { asm volatile("cp.async.wait_group %0;" :: "n"(N)); }
DEVFN void split_bf(float w, bf16& hi, bf16& lo) {
    hi = __float2bfloat16(w);
    lo = __float2bfloat16(w - __bfloat162float(hi));
}

// ======================================================================
// Packs
// ======================================================================
// Balanced-step W pack (fp16 hi/lo). dst layout per CTA:
// [tile16][plane2][u12][kb4][lane*4+reg*2+hh]. u<8: rec (gt=u>>1, hf=u&1);
// u>=8: z1x slice (4 n8).
__global__ void pack_bal(const float* __restrict__ W0, const float* __restrict__ W1,
                         f16* __restrict__ dst, int grp)
{
    size_t idx = (size_t)blockIdx.x * blockDim.x + threadIdx.x;
    if (idx >= WPACK) return;
    int inner = (int)(idx & 127);
    int kb    = (int)((idx >> 7) & 3);
    size_t q  = idx >> 9;
    int u     = (int)(q % 12); q /= 12;
    int plane = (int)(q & 1);  q >>= 1;
    int tile  = (int)(q & 15); q >>= 4;
    int cta   = (int)q;
    int lane = inner >> 2, reg = (inner >> 1) & 1, hh = inner & 1;
    int cc = lane >> 2, tg = lane & 3;
    int k = tile * 64 + kb * 16 + reg * 8 + tg * 2 + hh;
    int row, col; const float* src;
    if (u < 8) {
        int gt = u >> 1, hf = u & 1;
        col = gt * 1024 + cta * 16 + hf * 8 + cc;
        row = 1024 + k;
        src = grp ? W1 : W0;
    } else {
        col = (grp ? 2048 : 0) + cta * 32 + (u - 8) * 8 + cc;
        row = k;
        src = W1;
    }
    float w = src[(size_t)row * NGATE + col];
    f16 hi = __float2half(w);
    dst[idx] = plane ? __float2half(w - __half2float(hi)) : hi;
}

__global__ void pack_gemmW(const float* __restrict__ W, bf16* __restrict__ hi,
                           bf16* __restrict__ lo)
{
    size_t idx = (size_t)blockIdx.x * blockDim.x + threadIdx.x;
    if (idx >= (size_t)KDIM * NGATE) return;
    int k = (int)(idx >> 12), col = (int)(idx & 4095);
    int n8 = col >> 3, cc = col & 7;
    int kb = k >> 4, kl = k & 15;
    int reg = kl >> 3, tg = (kl >> 1) & 3, hh = kl & 1;
    int lane = cc * 4 + tg;
    size_t dst = ((size_t)n8 * 64 + kb) * 128 + lane * 4 + reg * 2 + hh;
    bf16 h, l; split_bf(W[idx], h, l);
    hi[dst] = h; lo[dst] = l;
}

__global__ void split_planes(const float* __restrict__ A, bf16* __restrict__ hi,
                             bf16* __restrict__ lo, size_t n)
{
    size_t idx = (size_t)blockIdx.x * blockDim.x + threadIdx.x;
    if (idx >= n) return;
    bf16 h, l; split_bf(A[idx], h, l);
    hi[idx] = h; lo[idx] = l;
}

// ======================================================================
// bf16 3-term Z0 pre-GEMM (proven R5 code)
// ======================================================================
#define GA_STRIDE 40
#define G_SA_BYTES 40960
#define G_SMEM (G_SA_BYTES + 32768)

__global__ __launch_bounds__(256) void gemm_bf16(
    const bf16* __restrict__ Ahi, const bf16* __restrict__ Alo,
    const bf16* __restrict__ Bhi, const bf16* __restrict__ Blo,
    const float* __restrict__ bias, float* __restrict__ C)
{
    extern __shared__ char smem[];
    bf16* sA = (bf16*)smem;
    bf16* sB = (bf16*)(smem + G_SA_BYTES);
    const int tid = threadIdx.x, warp = tid >> 5, lane = tid & 31;
    const int g = lane >> 2, t4 = lane & 3;
    const int wm = warp >> 1, wn = warp & 1;
    const int m0 = blockIdx.y * 128, n0 = blockIdx.x * 128, n8base = n0 >> 3;

    float acc[2][8][4];
    #pragma unroll
    for (int i = 0; i < 2; i++)
        #pragma unroll
        for (int j = 0; j < 8; j++)
            #pragma unroll
            for (int k = 0; k < 4; k++) acc[i][j][k] = 0.f;

    auto issue = [&](int ks, int s) {
        #pragma unroll
        for (int p = 0; p < 4; p++) {
            int id = p * 256 + tid;
            int plane = id >> 9, rem = id & 511;
            int row = rem >> 2, c8 = rem & 3;
            const bf16* src = (plane ? Alo : Ahi) + (size_t)(m0 + row) * KDIM + ks * 32 + c8 * 8;
            cp16(&sA[((size_t)(s * 2 + plane) * 128 + row) * GA_STRIDE + c8 * 8], src);
        }
        #pragma unroll
        for (int p = 0; p < 4; p++) {
            int id = p * 256 + tid;
            int plane = id >> 9, rem = id & 511;
            int n8l = rem >> 5, r32 = rem & 31;
            const bf16* src = (plane ? Blo : Bhi) + ((size_t)(n8base + n8l) * 64 + ks * 2) * 128 + r32 * 8;
            cp16(&sB[((size_t)(s * 2 + plane) * 16 + n8l) * 256 + r32 * 8], src);
        }
    };

    issue(0, 0); cp_commit();
    for (int ks = 0; ks < KDIM / 32; ks++) {
        cp_wait<0>(); __syncthreads();
        if (ks + 1 < KDIM / 32) issue(ks + 1, (ks + 1) & 1);
        cp_commit();
        const int s = ks & 1;
        #pragma unroll
        for (int kk = 0; kk < 2; kk++) {
            const int kloc = kk * 16 + t4 * 2;
            uint32_t ah[2][4], al[2][4];
            #pragma unroll
            for (int mf = 0; mf < 2; mf++) {
                int m = wm * 32 + mf * 16 + g;
                const bf16* p0 = &sA[((size_t)(s * 2) * 128 + m) * GA_STRIDE];
                const bf16* p1 = &sA[((size_t)(s * 2 + 1) * 128 + m) * GA_STRIDE];
                ah[mf][0] = *(const uint32_t*)(p0 + kloc);
                ah[mf][1] = *(const uint32_t*)(p0 + 8 * GA_STRIDE + kloc);
                ah[mf][2] = *(const uint32_t*)(p0 + kloc + 8);
                ah[mf][3] = *(const uint32_t*)(p0 + 8 * GA_STRIDE + kloc + 8);
                al[mf][0] = *(const uint32_t*)(p1 + kloc);
                al[mf][1] = *(const uint32_t*)(p1 + 8 * GA_STRIDE + kloc);
                al[mf][2] = *(const uint32_t*)(p1 + kloc + 8);
                al[mf][3] = *(const uint32_t*)(p1 + 8 * GA_STRIDE + kloc + 8);
            }
            #pragma unroll
            for (int nf = 0; nf < 8; nf++) {
                size_t base = ((size_t)(s * 2) * 16 + wn * 8 + nf) * 256 + kk * 128 + lane * 4;
                uint2 bhi = *(const uint2*)&sB[base];
                uint2 blo = *(const uint2*)&sB[base + 16 * 256];
                #pragma unroll
                for (int mf = 0; mf < 2; mf++) {
                    mma16b(acc[mf][nf], ah[mf], bhi);
                    mma16b(acc[mf][nf], al[mf], bhi);
                    mma16b(acc[mf][nf], ah[mf], blo);
                }
            }
        }
    }
    #pragma unroll
    for (int mf = 0; mf < 2; mf++)
        #pragma unroll
        for (int nf = 0; nf < 8; nf++) {
            int col = n0 + (wn * 8 + nf) * 8 + 2 * t4;
            int r0  = m0 + wm * 32 + mf * 16 + g;
            float bv0 = bias[col], bv1 = bias[col + 1];
            C[(size_t)r0 * NGATE + col]           = acc[mf][nf][0] + bv0;
            C[(size_t)r0 * NGATE + col + 1]       = acc[mf][nf][1] + bv1;
            C[(size_t)(r0 + 8) * NGATE + col]     = acc[mf][nf][2] + bv0;
            C[(size_t)(r0 + 8) * NGATE + col + 1] = acc[mf][nf][3] + bv1;
        }
}

// ======================================================================
// Balanced step launch t (0..257), 128 CTAs x 256 thr, K=1024 everywhere.
//  L0 CTA (0-63): L0-rec step t (A=h1[t-1], 4 rec units/warp)
//                 + z1x[s=t-1] cols 0:2048 (2 units/warp, same A).
//  L1 CTA (64-127): L1-rec step t-2 (A=h2[t-3], z from z1x ping-pong)
//                 + z1x[s=t-1] cols 2048:4096 (A=h1[t-1], 2nd A slot).
// 2-term fp16 W (exact). 768 HMMA/warp.
// ======================================================================
#define SH_STRIDE 72
#define A_BYTES (2 * 3 * 64 * SH_STRIDE * 2)     // 55296
#define B_HALFS 12288                            // per tile per CTA
#define S_SMEM (A_BYTES + 3 * B_HALFS * 2)       // 129024

__global__ __launch_bounds__(256, 1) void lstm_bal(
    int t, const float* __restrict__ Z0, const float* __restrict__ b1,
    f16* H1, f16* H2, const f16* __restrict__ hz,
    float* c0buf, float* c1buf, float* z1x,
    const f16* __restrict__ Wp0, const f16* __restrict__ Wp1, float* out)
{
    const bool isL1 = blockIdx.x >= 64;
    if (!isL1 && t == 257) return;
    if (isL1 && t == 0) return;
    const int cta = blockIdx.x & 63;

    extern __shared__ char smem[];
    f16* sA = (f16*)smem;                         // [slot2][stage3][64][72]
    f16* sB = (f16*)(smem + A_BYTES);             // [stage3][plane2][u12][kb4][128]

    const int tid = threadIdx.x, warp = tid >> 5, lane = tid & 31;
    const int g = lane >> 2, t4 = lane & 3;
    const int mw = warp & 3, ng = warp >> 2;
    const int mrow = mw * 16 + g;

    const bool zact   = (t >= 1 && t <= 256);
    const bool recact = isL1 ? (t >= 2) : (t <= 255);
    const int  sidx   = isL1 ? (t - 2) : t;       // rec step index
    const f16* a0src  = isL1 ? ((t >= 3) ? H2 + (size_t)(t - 3) * HSTEP : hz)
                             : (zact ? H1 + (size_t)(t - 1) * HSTEP : hz);
    const f16* a1src  = zact ? H1 + (size_t)(t - 1) * HSTEP : hz;
    const f16* Wp = (isL1 ? Wp1 : Wp0) + (size_t)cta * 196608;

    auto issue = [&](int tile, int st) {
        #pragma unroll
        for (int qq = 0; qq < 2; qq++) {
            int id = qq * 256 + tid;
            int row = id >> 3, c8 = id & 7;
            cp16(&sA[((size_t)st * 64 + row) * SH_STRIDE + c8 * 8],
                 a0src + (size_t)row * KDIM + tile * 64 + c8 * 8);
        }
        if (isL1) {
            #pragma unroll
            for (int qq = 0; qq < 2; qq++) {
                int id = qq * 256 + tid;
                int row = id >> 3, c8 = id & 7;
                cp16(&sA[((size_t)(3 + st) * 64 + row) * SH_STRIDE + c8 * 8],
                     a1src + (size_t)row * KDIM + tile * 64 + c8 * 8);
            }
        }
        #pragma unroll
        for (int qq = 0; qq < 6; qq++) {
            int id = qq * 256 + tid;
            cp16(&sB[(size_t)st * B_HALFS + id * 8],
                 Wp + (size_t)tile * B_HALFS + id * 8);
        }
    };

    float acc[6][4];
    #pragma unroll
    for (int i = 0; i < 6; i++)
        #pragma unroll
        for (int e = 0; e < 4; e++) acc[i][e] = 0.f;

    issue(0, 0); cp_commit();
    issue(1, 1); cp_commit();

    for (int tile = 0; tile < 16; tile++) {
        cp_wait<1>(); __syncthreads();
        if (tile + 2 < 16) issue(tile + 2, (tile + 2) % 3);
        cp_commit();
        const int st = tile % 3;
        const f16* A0 = &sA[(size_t)st * 64 * SH_STRIDE];
        const f16* A1 = isL1 ? &sA[(size_t)(3 + st) * 64 * SH_STRIDE] : A0;
        const f16* B  = &sB[(size_t)st * B_HALFS];

        #pragma unroll
        for (int kb = 0; kb < 4; kb++) {
            const int kloc = kb * 16 + t4 * 2;
            uint32_t a0[4], a1[4];
            a0[0] = *(const uint32_t*)(A0 + (size_t)mrow * SH_STRIDE + kloc);
            a0[1] = *(const uint32_t*)(A0 + (size_t)(mrow + 8) * SH_STRIDE + kloc);
            a0[2] = *(const uint32_t*)(A0 + (size_t)mrow * SH_STRIDE + kloc + 8);
            a0[3] = *(const uint32_t*)(A0 + (size_t)(mrow + 8) * SH_STRIDE + kloc + 8);
            if (isL1) {
                a1[0] = *(const uint32_t*)(A1 + (size_t)mrow * SH_STRIDE + kloc);
                a1[1] = *(const uint32_t*)(A1 + (size_t)(mrow + 8) * SH_STRIDE + kloc);
                a1[2] = *(const uint32_t*)(A1 + (size_t)mrow * SH_STRIDE + kloc + 8);
                a1[3] = *(const uint32_t*)(A1 + (size_t)(mrow + 8) * SH_STRIDE + kloc + 8);
            } else {
                a1[0] = a0[0]; a1[1] = a0[1]; a1[2] = a0[2]; a1[3] = a0[3];
            }
            #pragma unroll
            for (int gt = 0; gt < 4; gt++) {
                int u = gt * 2 + ng;
                uint2 bh = *(const uint2*)&B[(size_t)(0 * 12 + u) * 512 + kb * 128 + lane * 4];
                uint2 bl = *(const uint2*)&B[(size_t)(1 * 12 + u) * 512 + kb * 128 + lane * 4];
                mma16f(acc[gt], a0, bh);
                mma16f(acc[gt], a0, bl);
            }
            #pragma unroll
            for (int zz = 0; zz < 2; zz++) {
                int u = 8 + ng * 2 + zz;
                uint2 bh = *(const uint2*)&B[(size_t)(0 * 12 + u) * 512 + kb * 128 + lane * 4];
                uint2 bl = *(const uint2*)&B[(size_t)(1 * 12 + u) * 512 + kb * 128 + lane * 4];
                mma16f(acc[4 + zz], a1, bh);
                mma16f(acc[4 + zz], a1, bl);
            }
        }
    }

    // ---- rec epilogue ----
    if (recact) {
        float* cb = isL1 ? c1buf : c0buf;
        const bool first = (sidx == 0);
        const int n0r = cta * 16 + ng * 8;
        const float* zrd = isL1 ? (z1x + (size_t)(sidx & 1) * ZSTEP)
                                : (Z0 + (size_t)t * ZSTEP);
        #pragma unroll
        for (int e = 0; e < 4; e++) {
            int row = mrow + (e >> 1) * 8;
            int col = n0r + t4 * 2 + (e & 1);
            const float* zr = zrd + (size_t)row * NGATE;
            float zi = acc[0][e] + __ldg(zr + col);
            float zj = acc[1][e] + __ldg(zr + 1024 + col);
            float zf = acc[2][e] + __ldg(zr + 2048 + col);
            float zo = acc[3][e] + __ldg(zr + 3072 + col);
            float cold = first ? 0.f : cb[(size_t)row * KDIM + col];
            float ig = 1.f / (1.f + expf(-zi));
            float fg = 1.f / (1.f + expf(-(zf + 1.f)));   // FORGET_BIAS = 1.0
            float og = 1.f / (1.f + expf(-zo));
            float cn = cold * fg + ig * tanhf(zj);
            float hv = tanhf(cn) * og;
            cb[(size_t)row * KDIM + col] = cn;
            if (isL1) {
                out[(size_t)sidx * HSTEP + (size_t)row * KDIM + col] = hv;
                H2[(size_t)sidx * HSTEP + (size_t)row * KDIM + col] = __float2half(hv);
            } else {
                H1[(size_t)t * HSTEP + (size_t)row * KDIM + col] = __float2half(hv);
            }
        }
    }

    // ---- z1x epilogue (b1 added here) ----
    if (zact) {
        const int s = t - 1;
        float* zw = z1x + (size_t)(s & 1) * ZSTEP;
        const int zbase = (isL1 ? 2048 : 0) + cta * 32 + ng * 16;
        #pragma unroll
        for (int zz = 0; zz < 2; zz++)
            #pragma unroll
            for (int e = 0; e < 4; e++) {
                int row = mrow + (e >> 1) * 8;
                int col = zbase + zz * 8 + t4 * 2 + (e & 1);
                zw[(size_t)row * NGATE + col] = acc[4 + zz][e] + __ldg(b1 + col);
            }
    }
}

// ======================================================================
extern "C" void kernel_launch(void* const* d_in, const int* in_sizes, int n_in,
                              void* d_out, int out_size)
{
    const float* X  = (const float*)d_in[0];
    const float* W0 = (const float*)d_in[1];
    const float* b0 = (const float*)d_in[2];
    const float* W1 = (const float*)d_in[3];
    const float* b1 = (const float*)d_in[4];
    float* out = (float*)d_out;

    float *Z0, *c0, *c1, *z1x;
    bf16 *Xhi, *Xlo, *Wg0;
    f16 *H1, *H2, *hz, *WpL0, *WpL1;
    cudaGetSymbolAddress((void**)&Z0,   g_Z0);
    cudaGetSymbolAddress((void**)&c0,   g_c0);
    cudaGetSymbolAddress((void**)&c1,   g_c1);
    cudaGetSymbolAddress((void**)&z1x,  g_z1x);
    cudaGetSymbolAddress((void**)&Xhi,  g_Xhi);
    cudaGetSymbolAddress((void**)&Xlo,  g_Xlo);
    cudaGetSymbolAddress((void**)&Wg0,  g_Wg0);
    cudaGetSymbolAddress((void**)&H1,   g_H1);
    cudaGetSymbolAddress((void**)&H2,   g_H2);
    cudaGetSymbolAddress((void**)&hz,   g_hz);
    cudaGetSymbolAddress((void**)&WpL0, g_WpL0);
    cudaGetSymbolAddress((void**)&WpL1, g_WpL1);

    const size_t WP0 = (size_t)KDIM * NGATE;
    const size_t NX  = (size_t)T_STEPS * HSTEP;

    cudaFuncSetAttribute(gemm_bf16, cudaFuncAttributeMaxDynamicSharedMemorySize, G_SMEM);
    cudaFuncSetAttribute(lstm_bal,  cudaFuncAttributeMaxDynamicSharedMemorySize, S_SMEM);

    const int pb = 256;
    pack_gemmW<<<(int)((WP0 + pb - 1) / pb), pb>>>(W0, Wg0, Wg0 + WP0);
    pack_bal<<<(int)((WPACK + pb - 1) / pb), pb>>>(W0, W1, WpL0, 0);
    pack_bal<<<(int)((WPACK + pb - 1) / pb), pb>>>(W0, W1, WpL1, 1);
    split_planes<<<(int)((NX + 255) / 256), 256>>>(X, Xhi, Xlo, NX);

    gemm_bf16<<<dim3(NGATE / 128, (T_STEPS * BATCH) / 128), 256, G_SMEM>>>(
        Xhi, Xlo, Wg0, Wg0 + WP0, b0, Z0);

    for (int t = 0; t <= 257; t++) {
        lstm_bal<<<128, 256, S_SMEM>>>(
            t, Z0, b1, H1, H2, hz, c0, c1, z1x, WpL0, WpL1, out);
    }
}

// round 12
// speedup vs baseline: 1.5974x; 1.1662x over previous
#include <cuda_runtime.h>
#include <cuda_fp16.h>
#include <cstdint>
#include <cmath>

#define T_STEPS 256
#define BATCH   64
#define KDIM    1024
#define NGATE   4096
#define HSTEP   ((size_t)BATCH * KDIM)
#define ZSTEP   ((size_t)BATCH * NGATE)

typedef __half f16;

// ---------------- scratch globals ----------------
__device__ float g_Z0[(size_t)T_STEPS * BATCH * NGATE];
__device__ f16   g_X16[(size_t)T_STEPS * BATCH * KDIM];
__device__ f16   g_Wg0[2][(size_t)KDIM * NGATE];        // Z0 W, fp16 hi/lo
__device__ f16   g_H1[(size_t)T_STEPS * BATCH * KDIM];
__device__ f16   g_H2[(size_t)T_STEPS * BATCH * KDIM];
__device__ f16   g_hz[BATCH * KDIM];                    // never written: zeros
__device__ float g_c0[BATCH * KDIM];
__device__ float g_c1[BATCH * KDIM];
__device__ float g_z1x[2][BATCH * NGATE];               // ping-pong, b1 included
// step W pack: per CTA [tile16][uu20][512]; uu<12 = hi(8 rec + 4 z), uu>=12 = lo rec(8)
#define B2_HALFS 10240
#define WPACK ((size_t)64 * 16 * B2_HALFS)              // 10,485,760 halfs
__device__ f16   g_WpL0[WPACK];
__device__ f16   g_WpL1[WPACK];

#define DEVFN __device__ __forceinline__

DEVFN void mma16f(float* c, const uint32_t* a, uint2 b) {
    asm volatile("mma.sync.aligned.m16n8k16.row.col.f32.f16.f16.f32 "
        "{%0,%1,%2,%3},{%4,%5,%6,%7},{%8,%9},{%0,%1,%2,%3};"
        : "+f"(c[0]), "+f"(c[1]), "+f"(c[2]), "+f"(c[3])
        : "r"(a[0]), "r"(a[1]), "r"(a[2]), "r"(a[3]), "r"(b.x), "r"(b.y));
}
DEVFN void cp16(void* s, const void* g) {
    uint32_t sa = (uint32_t)__cvta_generic_to_shared(s);
    asm volatile("cp.async.cg.shared.global [%0], [%1], 16;" :: "r"(sa), "l"(g));
}
DEVFN void cp_commit() { asm volatile("cp.async.commit_group;"); }
template <int N> DEVFN void cp_wait() { asm volatile("cp.async.wait_group %0;" :: "n"(N)); }

// ======================================================================
// Packs
// ======================================================================
// Step W pack. inner = [kb4][128]; uu<12: hi plane u=uu (u<8 rec: gt=u>>1,hf=u&1;
// u in 8..11: z slice); uu>=12: lo plane rec unit u=uu-12.
__global__ void pack_bal(const float* __restrict__ W0, const float* __restrict__ W1,
                         f16* __restrict__ dst, int grp)
{
    size_t idx = (size_t)blockIdx.x * blockDim.x + threadIdx.x;
    if (idx >= WPACK) return;
    int inner = (int)(idx & 127);
    int kb    = (int)((idx >> 7) & 3);
    size_t q  = idx >> 9;
    int uu    = (int)(q % 20); q /= 20;
    int tile  = (int)(q & 15); q >>= 4;
    int cta   = (int)q;
    int plane = (uu >= 12), u = plane ? (uu - 12) : uu;
    int lane = inner >> 2, reg = (inner >> 1) & 1, hh = inner & 1;
    int cc = lane >> 2, tg = lane & 3;
    int k = tile * 64 + kb * 16 + reg * 8 + tg * 2 + hh;
    int row, col; const float* src;
    if (u < 8) {
        int gt = u >> 1, hf = u & 1;
        col = gt * 1024 + cta * 16 + hf * 8 + cc;
        row = 1024 + k;
        src = grp ? W1 : W0;
    } else {                       // z units: hi plane only (u 8..11)
        col = (grp ? 2048 : 0) + cta * 32 + (u - 8) * 8 + cc;
        row = k;
        src = W1;
    }
    float w = src[(size_t)row * NGATE + col];
    f16 hi = __float2half(w);
    dst[idx] = plane ? __float2half(w - __half2float(hi)) : hi;
}

// Z0 pre-GEMM pack (fp16 hi/lo, fragment order)
__global__ void pack_gemmW(const float* __restrict__ W, f16* __restrict__ hi,
                           f16* __restrict__ lo)
{
    size_t idx = (size_t)blockIdx.x * blockDim.x + threadIdx.x;
    if (idx >= (size_t)KDIM * NGATE) return;
    int k = (int)(idx >> 12), col = (int)(idx & 4095);
    int n8 = col >> 3, cc = col & 7;
    int kb = k >> 4, kl = k & 15;
    int reg = kl >> 3, tg = (kl >> 1) & 3, hh = kl & 1;
    int lane = cc * 4 + tg;
    size_t dst = ((size_t)n8 * 64 + kb) * 128 + lane * 4 + reg * 2 + hh;
    float w = W[idx];
    f16 h = __float2half(w);
    hi[dst] = h;
    lo[dst] = __float2half(w - __half2float(h));
}

__global__ void cvt_f16(const float* __restrict__ A, f16* __restrict__ B, size_t n)
{
    size_t idx = (size_t)blockIdx.x * blockDim.x + threadIdx.x;
    if (idx < n) B[idx] = __float2half(A[idx]);
}

// ======================================================================
// Z0 pre-GEMM: single-fp16 A x 2-term-fp16 W. Tile 128x128x32, 256 thr.
// ======================================================================
#define GA_STRIDE 40
#define G_SA_BYTES (2 * 128 * GA_STRIDE * 2)          // 20480
#define G_SMEM (G_SA_BYTES + 2 * 2 * 16 * 256 * 2)    // + 32768 = 53248

__global__ __launch_bounds__(256) void gemm_z0(
    const f16* __restrict__ A, const f16* __restrict__ Bhi, const f16* __restrict__ Blo,
    const float* __restrict__ bias, float* __restrict__ C)
{
    extern __shared__ char smem[];
    f16* sA = (f16*)smem;
    f16* sB = (f16*)(smem + G_SA_BYTES);
    const int tid = threadIdx.x, warp = tid >> 5, lane = tid & 31;
    const int g = lane >> 2, t4 = lane & 3;
    const int wm = warp >> 1, wn = warp & 1;
    const int m0 = blockIdx.y * 128, n0 = blockIdx.x * 128, n8base = n0 >> 3;

    float acc[2][8][4];
    #pragma unroll
    for (int i = 0; i < 2; i++)
        #pragma unroll
        for (int j = 0; j < 8; j++)
            #pragma unroll
            for (int k = 0; k < 4; k++) acc[i][j][k] = 0.f;

    auto issue = [&](int ks, int s) {
        #pragma unroll
        for (int p = 0; p < 2; p++) {                 // A: 512 cp16
            int id = p * 256 + tid;
            int row = id >> 2, c8 = id & 3;
            cp16(&sA[((size_t)s * 128 + row) * GA_STRIDE + c8 * 8],
                 A + (size_t)(m0 + row) * KDIM + ks * 32 + c8 * 8);
        }
        #pragma unroll
        for (int p = 0; p < 4; p++) {                 // B: 1024 cp16 (2 planes)
            int id = p * 256 + tid;
            int plane = id >> 9, rem = id & 511;
            int n8l = rem >> 5, r32 = rem & 31;
            const f16* src = (plane ? Blo : Bhi)
                + ((size_t)(n8base + n8l) * 64 + ks * 2) * 128 + r32 * 8;
            cp16(&sB[((size_t)(s * 2 + plane) * 16 + n8l) * 256 + r32 * 8], src);
        }
    };

    issue(0, 0); cp_commit();
    for (int ks = 0; ks < KDIM / 32; ks++) {
        cp_wait<0>(); __syncthreads();
        if (ks + 1 < KDIM / 32) issue(ks + 1, (ks + 1) & 1);
        cp_commit();
        const int s = ks & 1;
        #pragma unroll
        for (int kk = 0; kk < 2; kk++) {
            const int kloc = kk * 16 + t4 * 2;
            uint32_t a[2][4];
            #pragma unroll
            for (int mf = 0; mf < 2; mf++) {
                int m = wm * 32 + mf * 16 + g;
                const f16* p0 = &sA[((size_t)s * 128 + m) * GA_STRIDE];
                a[mf][0] = *(const uint32_t*)(p0 + kloc);
                a[mf][1] = *(const uint32_t*)(p0 + 8 * GA_STRIDE + kloc);
                a[mf][2] = *(const uint32_t*)(p0 + kloc + 8);
                a[mf][3] = *(const uint32_t*)(p0 + 8 * GA_STRIDE + kloc + 8);
            }
            #pragma unroll
            for (int nf = 0; nf < 8; nf++) {
                size_t base = ((size_t)(s * 2) * 16 + wn * 8 + nf) * 256 + kk * 128 + lane * 4;
                uint2 bh = *(const uint2*)&sB[base];
                uint2 bl = *(const uint2*)&sB[base + 16 * 256];
                #pragma unroll
                for (int mf = 0; mf < 2; mf++) {
                    mma16f(acc[mf][nf], a[mf], bh);
                    mma16f(acc[mf][nf], a[mf], bl);
                }
            }
        }
    }
    #pragma unroll
    for (int mf = 0; mf < 2; mf++)
        #pragma unroll
        for (int nf = 0; nf < 8; nf++) {
            int col = n0 + (wn * 8 + nf) * 8 + 2 * t4;
            int r0  = m0 + wm * 32 + mf * 16 + g;
            float bv0 = bias[col], bv1 = bias[col + 1];
            C[(size_t)r0 * NGATE + col]           = acc[mf][nf][0] + bv0;
            C[(size_t)r0 * NGATE + col + 1]       = acc[mf][nf][1] + bv1;
            C[(size_t)(r0 + 8) * NGATE + col]     = acc[mf][nf][2] + bv0;
            C[(size_t)(r0 + 8) * NGATE + col + 1] = acc[mf][nf][3] + bv1;
        }
}

// ======================================================================
// Balanced step launch t (0..257), 128 CTAs x 256 thr (structure = R11):
//  L0 CTA: L0-rec step t (2-term) + z1x[s=t-1] cols 0:2048 (1-term).
//  L1 CTA: L1-rec step t-2 (2-term, z from ping-pong) + z1x cols 2048:4096.
// 640 HMMA/warp. z-term & c prefetched into regs before the MMA loop.
// ======================================================================
#define SH_STRIDE 72
#define A_BYTES (2 * 3 * 64 * SH_STRIDE * 2)     // 55296
#define S_SMEM (A_BYTES + 3 * B2_HALFS * 2)      // + 61440 = 116736

__global__ __launch_bounds__(256, 1) void lstm_bal(
    int t, const float* __restrict__ Z0, const float* __restrict__ b1,
    f16* H1, f16* H2, const f16* __restrict__ hz,
    float* c0buf, float* c1buf, float* z1x,
    const f16* __restrict__ Wp0, const f16* __restrict__ Wp1, float* out)
{
    const bool isL1 = blockIdx.x >= 64;
    if (!isL1 && t == 257) return;
    if (isL1 && t == 0) return;
    const int cta = blockIdx.x & 63;

    extern __shared__ char smem[];
    f16* sA = (f16*)smem;                         // [slot2][stage3][64][72]
    f16* sB = (f16*)(smem + A_BYTES);             // [stage3][uu20][512]

    const int tid = threadIdx.x, warp = tid >> 5, lane = tid & 31;
    const int g = lane >> 2, t4 = lane & 3;
    const int mw = warp & 3, ng = warp >> 2;
    const int mrow = mw * 16 + g;

    const bool zact   = (t >= 1 && t <= 256);
    const bool recact = isL1 ? (t >= 2) : (t <= 255);
    const int  sidx   = isL1 ? (t - 2) : t;
    const f16* a0src  = isL1 ? ((t >= 3) ? H2 + (size_t)(t - 3) * HSTEP : hz)
                             : (zact ? H1 + (size_t)(t - 1) * HSTEP : hz);
    const f16* a1src  = zact ? H1 + (size_t)(t - 1) * HSTEP : hz;
    const f16* Wp = (isL1 ? Wp1 : Wp0) + (size_t)cta * (16 * (size_t)B2_HALFS);

    auto issue = [&](int tile, int st) {
        #pragma unroll
        for (int qq = 0; qq < 2; qq++) {
            int id = qq * 256 + tid;
            int row = id >> 3, c8 = id & 7;
            cp16(&sA[((size_t)st * 64 + row) * SH_STRIDE + c8 * 8],
                 a0src + (size_t)row * KDIM + tile * 64 + c8 * 8);
        }
        if (isL1) {
            #pragma unroll
            for (int qq = 0; qq < 2; qq++) {
                int id = qq * 256 + tid;
                int row = id >> 3, c8 = id & 7;
                cp16(&sA[((size_t)(3 + st) * 64 + row) * SH_STRIDE + c8 * 8],
                     a1src + (size_t)row * KDIM + tile * 64 + c8 * 8);
            }
        }
        #pragma unroll
        for (int qq = 0; qq < 5; qq++) {             // B: 1280 cp16
            int id = qq * 256 + tid;
            cp16(&sB[(size_t)st * B2_HALFS + id * 8],
                 Wp + (size_t)tile * B2_HALFS + id * 8);
        }
    };

    // ---- register prefetch of z-term and c-state (hidden under MMA loop) ----
    const int n0r = cta * 16 + ng * 8;
    float zr[4][4], cold[4] = {0.f, 0.f, 0.f, 0.f};
    if (recact) {
        const float* zrd = isL1 ? (z1x + (size_t)(sidx & 1) * ZSTEP)
                                : (Z0 + (size_t)t * ZSTEP);
        #pragma unroll
        for (int gt = 0; gt < 4; gt++)
            #pragma unroll
            for (int rr = 0; rr < 2; rr++) {
                float2 v = __ldg((const float2*)(zrd + (size_t)(mrow + rr * 8) * NGATE
                                                 + gt * 1024 + n0r + t4 * 2));
                zr[gt][rr * 2] = v.x; zr[gt][rr * 2 + 1] = v.y;
            }
        if (sidx > 0) {
            const float* cb = isL1 ? c1buf : c0buf;
            #pragma unroll
            for (int rr = 0; rr < 2; rr++) {
                float2 cv = __ldg((const float2*)(cb + (size_t)(mrow + rr * 8) * KDIM
                                                  + n0r + t4 * 2));
                cold[rr * 2] = cv.x; cold[rr * 2 + 1] = cv.y;
            }
        }
    }

    float acc[6][4];
    #pragma unroll
    for (int i = 0; i < 6; i++)
        #pragma unroll
        for (int e = 0; e < 4; e++) acc[i][e] = 0.f;

    issue(0, 0); cp_commit();
    issue(1, 1); cp_commit();

    for (int tile = 0; tile < 16; tile++) {
        cp_wait<1>(); __syncthreads();
        if (tile + 2 < 16) issue(tile + 2, (tile + 2) % 3);
        cp_commit();
        const int st = tile % 3;
        const f16* A0 = &sA[(size_t)st * 64 * SH_STRIDE];
        const f16* A1 = isL1 ? &sA[(size_t)(3 + st) * 64 * SH_STRIDE] : A0;
        const f16* B  = &sB[(size_t)st * B2_HALFS];

        #pragma unroll
        for (int kb = 0; kb < 4; kb++) {
            const int kloc = kb * 16 + t4 * 2;
            uint32_t a0[4], a1[4];
            a0[0] = *(const uint32_t*)(A0 + (size_t)mrow * SH_STRIDE + kloc);
            a0[1] = *(const uint32_t*)(A0 + (size_t)(mrow + 8) * SH_STRIDE + kloc);
            a0[2] = *(const uint32_t*)(A0 + (size_t)mrow * SH_STRIDE + kloc + 8);
            a0[3] = *(const uint32_t*)(A0 + (size_t)(mrow + 8) * SH_STRIDE + kloc + 8);
            if (isL1) {
                a1[0] = *(const uint32_t*)(A1 + (size_t)mrow * SH_STRIDE + kloc);
                a1[1] = *(const uint32_t*)(A1 + (size_t)(mrow + 8) * SH_STRIDE + kloc);
                a1[2] = *(const uint32_t*)(A1 + (size_t)mrow * SH_STRIDE + kloc + 8);
                a1[3] = *(const uint32_t*)(A1 + (size_t)(mrow + 8) * SH_STRIDE + kloc + 8);
            } else {
                a1[0] = a0[0]; a1[1] = a0[1]; a1[2] = a0[2]; a1[3] = a0[3];
            }
            #pragma unroll
            for (int gt = 0; gt < 4; gt++) {        // rec: 2-term
                int u = gt * 2 + ng;
                uint2 bh = *(const uint2*)&B[(size_t)u * 512 + kb * 128 + lane * 4];
                uint2 bl = *(const uint2*)&B[(size_t)(12 + u) * 512 + kb * 128 + lane * 4];
                mma16f(acc[gt], a0, bh);
                mma16f(acc[gt], a0, bl);
            }
            #pragma unroll
            for (int zz = 0; zz < 2; zz++) {        // z1x: 1-term
                int u = 8 + ng * 2 + zz;
                uint2 bh = *(const uint2*)&B[(size_t)u * 512 + kb * 128 + lane * 4];
                mma16f(acc[4 + zz], a1, bh);
            }
        }
    }

    // ---- rec epilogue ----
    if (recact) {
        float* cb = isL1 ? c1buf : c0buf;
        #pragma unroll
        for (int e = 0; e < 4; e++) {
            int row = mrow + (e >> 1) * 8;
            int col = n0r + t4 * 2 + (e & 1);
            float zi = acc[0][e] + zr[0][e];
            float zj = acc[1][e] + zr[1][e];
            float zf = acc[2][e] + zr[2][e];
            float zo = acc[3][e] + zr[3][e];
            float ig = 1.f / (1.f + expf(-zi));
            float fg = 1.f / (1.f + expf(-(zf + 1.f)));   // FORGET_BIAS = 1.0
            float og = 1.f / (1.f + expf(-zo));
            float cn = cold[e] * fg + ig * tanhf(zj);
            float hv = tanhf(cn) * og;
            cb[(size_t)row * KDIM + col] = cn;
            if (isL1) {
                out[(size_t)sidx * HSTEP + (size_t)row * KDIM + col] = hv;
                H2[(size_t)sidx * HSTEP + (size_t)row * KDIM + col] = __float2half(hv);
            } else {
                H1[(size_t)t * HSTEP + (size_t)row * KDIM + col] = __float2half(hv);
            }
        }
    }

    // ---- z1x epilogue (b1 added here) ----
    if (zact) {
        const int s = t - 1;
        float* zw = z1x + (size_t)(s & 1) * ZSTEP;
        const int zbase = (isL1 ? 2048 : 0) + cta * 32 + ng * 16;
        #pragma unroll
        for (int zz = 0; zz < 2; zz++)
            #pragma unroll
            for (int e = 0; e < 4; e++) {
                int row = mrow + (e >> 1) * 8;
                int col = zbase + zz * 8 + t4 * 2 + (e & 1);
                zw[(size_t)row * NGATE + col] = acc[4 + zz][e] + __ldg(b1 + col);
            }
    }
}

// ======================================================================
extern "C" void kernel_launch(void* const* d_in, const int* in_sizes, int n_in,
                              void* d_out, int out_size)
{
    const float* X  = (const float*)d_in[0];
    const float* W0 = (const float*)d_in[1];
    const float* b0 = (const float*)d_in[2];
    const float* W1 = (const float*)d_in[3];
    const float* b1 = (const float*)d_in[4];
    float* out = (float*)d_out;

    float *Z0, *c0, *c1, *z1x;
    f16 *X16, *Wg0, *H1, *H2, *hz, *WpL0, *WpL1;
    cudaGetSymbolAddress((void**)&Z0,   g_Z0);
    cudaGetSymbolAddress((void**)&c0,   g_c0);
    cudaGetSymbolAddress((void**)&c1,   g_c1);
    cudaGetSymbolAddress((void**)&z1x,  g_z1x);
    cudaGetSymbolAddress((void**)&X16,  g_X16);
    cudaGetSymbolAddress((void**)&Wg0,  g_Wg0);
    cudaGetSymbolAddress((void**)&H1,   g_H1);
    cudaGetSymbolAddress((void**)&H2,   g_H2);
    cudaGetSymbolAddress((void**)&hz,   g_hz);
    cudaGetSymbolAddress((void**)&WpL0, g_WpL0);
    cudaGetSymbolAddress((void**)&WpL1, g_WpL1);

    const size_t WP0 = (size_t)KDIM * NGATE;
    const size_t NX  = (size_t)T_STEPS * HSTEP;

    cudaFuncSetAttribute(gemm_z0,  cudaFuncAttributeMaxDynamicSharedMemorySize, G_SMEM);
    cudaFuncSetAttribute(lstm_bal, cudaFuncAttributeMaxDynamicSharedMemorySize, S_SMEM);

    const int pb = 256;
    pack_gemmW<<<(int)((WP0 + pb - 1) / pb), pb>>>(W0, Wg0, Wg0 + WP0);
    pack_bal<<<(int)((WPACK + pb - 1) / pb), pb>>>(W0, W1, WpL0, 0);
    pack_bal<<<(int)((WPACK + pb - 1) / pb), pb>>>(W0, W1, WpL1, 1);
    cvt_f16<<<(int)((NX + 255) / 256), 256>>>(X, X16, NX);

    gemm_z0<<<dim3(NGATE / 128, (T_STEPS * BATCH) / 128), 256, G_SMEM>>>(
        X16, Wg0, Wg0 + WP0, b0, Z0);

    for (int t = 0; t <= 257; t++) {
        lstm_bal<<<128, 256, S_SMEM>>>(
            t, Z0, b1, H1, H2, hz, c0, c1, z1x, WpL0, WpL1, out);
    }
}

// round 14
// speedup vs baseline: 1.6902x; 1.0581x over previous
#include <cuda_runtime.h>
#include <cuda_fp16.h>
#include <cstdint>
#include <cmath>

#define T_STEPS 256
#define BATCH   64
#define KDIM    1024
#define NGATE   4096
#define HSTEP   ((size_t)BATCH * KDIM)
#define ZSTEP   ((size_t)BATCH * NGATE)

typedef __half f16;

// ---------------- scratch globals ----------------
__device__ float g_Z0[(size_t)T_STEPS * BATCH * NGATE];
__device__ f16   g_X16[(size_t)T_STEPS * BATCH * KDIM];
__device__ f16   g_Wg0[2][(size_t)KDIM * NGATE];        // Z0 W, fp16 hi/lo
__device__ f16   g_H1[(size_t)T_STEPS * BATCH * KDIM];
__device__ f16   g_H2[(size_t)T_STEPS * BATCH * KDIM];
__device__ f16   g_hz[BATCH * KDIM];                    // never written: zeros
__device__ float g_c0[BATCH * KDIM];
__device__ float g_c1[BATCH * KDIM];
__device__ float g_z1x[2][BATCH * NGATE];               // ping-pong, b1 included
// step W pack: per CTA [ktile16][uu20][kb4][128]
#define B2_HALFS 10240
#define WPACK ((size_t)64 * 16 * B2_HALFS)
__device__ f16   g_WpL0[WPACK];
__device__ f16   g_WpL1[WPACK];

#define DEVFN __device__ __forceinline__

DEVFN void mma16f(float* c, const uint32_t* a, uint2 b) {
    asm volatile("mma.sync.aligned.m16n8k16.row.col.f32.f16.f16.f32 "
        "{%0,%1,%2,%3},{%4,%5,%6,%7},{%8,%9},{%0,%1,%2,%3};"
        : "+f"(c[0]), "+f"(c[1]), "+f"(c[2]), "+f"(c[3])
        : "r"(a[0]), "r"(a[1]), "r"(a[2]), "r"(a[3]), "r"(b.x), "r"(b.y));
}
// fp16-accumulator variant (2x rate): ONLY for the tiny lo-plane rec term
DEVFN void mma16h(uint32_t* c, const uint32_t* a, uint2 b) {
    asm volatile("mma.sync.aligned.m16n8k16.row.col.f16.f16.f16.f16 "
        "{%0,%1},{%2,%3,%4,%5},{%6,%7},{%0,%1};"
        : "+r"(c[0]), "+r"(c[1])
        : "r"(a[0]), "r"(a[1]), "r"(a[2]), "r"(a[3]), "r"(b.x), "r"(b.y));
}
DEVFN void cp16(void* s, const void* g) {
    uint32_t sa = (uint32_t)__cvta_generic_to_shared(s);
    asm volatile("cp.async.cg.shared.global [%0], [%1], 16;" :: "r"(sa), "l"(g));
}
DEVFN void cp_commit() { asm volatile("cp.async.commit_group;"); }
template <int N> DEVFN void cp_wait() { asm volatile("cp.async.wait_group %0;" :: "n"(N)); }

// ======================================================================
// Packs
// ======================================================================
__global__ void pack_bal(const float* __restrict__ W0, const float* __restrict__ W1,
                         f16* __restrict__ dst, int grp)
{
    size_t idx = (size_t)blockIdx.x * blockDim.x + threadIdx.x;
    if (idx >= WPACK) return;
    int inner = (int)(idx & 127);
    int kb    = (int)((idx >> 7) & 3);
    size_t q  = idx >> 9;
    int uu    = (int)(q % 20); q /= 20;
    int tile  = (int)(q & 15); q >>= 4;
    int cta   = (int)q;
    int plane = (uu >= 12), u = plane ? (uu - 12) : uu;
    int lane = inner >> 2, reg = (inner >> 1) & 1, hh = inner & 1;
    int cc = lane >> 2, tg = lane & 3;
    int k = tile * 64 + kb * 16 + reg * 8 + tg * 2 + hh;
    int row, col; const float* src;
    if (u < 8) {
        int gt = u >> 1, hf = u & 1;
        col = gt * 1024 + cta * 16 + hf * 8 + cc;
        row = 1024 + k;
        src = grp ? W1 : W0;
    } else {
        col = (grp ? 2048 : 0) + cta * 32 + (u - 8) * 8 + cc;
        row = k;
        src = W1;
    }
    float w = src[(size_t)row * NGATE + col];
    f16 hi = __float2half(w);
    dst[idx] = plane ? __float2half(w - __half2float(hi)) : hi;
}

__global__ void pack_gemmW(const float* __restrict__ W, f16* __restrict__ hi,
                           f16* __restrict__ lo)
{
    size_t idx = (size_t)blockIdx.x * blockDim.x + threadIdx.x;
    if (idx >= (size_t)KDIM * NGATE) return;
    int k = (int)(idx >> 12), col = (int)(idx & 4095);
    int n8 = col >> 3, cc = col & 7;
    int kb = k >> 4, kl = k & 15;
    int reg = kl >> 3, tg = (kl >> 1) & 3, hh = kl & 1;
    int lane = cc * 4 + tg;
    size_t dst = ((size_t)n8 * 64 + kb) * 128 + lane * 4 + reg * 2 + hh;
    float w = W[idx];
    f16 h = __float2half(w);
    hi[dst] = h;
    lo[dst] = __float2half(w - __half2float(h));
}

__global__ void cvt_f16(const float* __restrict__ A, f16* __restrict__ B, size_t n)
{
    size_t idx = (size_t)blockIdx.x * blockDim.x + threadIdx.x;
    if (idx < n) B[idx] = __float2half(A[idx]);
}

// ======================================================================
// Z0 pre-GEMM: single-fp16 A x 2-term-fp16 W. Tile 128x128x32, 256 thr.
// ======================================================================
#define GA_STRIDE 40
#define G_SA_BYTES (2 * 128 * GA_STRIDE * 2)
#define G_SMEM (G_SA_BYTES + 2 * 2 * 16 * 256 * 2)

__global__ __launch_bounds__(256) void gemm_z0(
    const f16* __restrict__ A, const f16* __restrict__ Bhi, const f16* __restrict__ Blo,
    const float* __restrict__ bias, float* __restrict__ C)
{
    extern __shared__ char smem[];
    f16* sA = (f16*)smem;
    f16* sB = (f16*)(smem + G_SA_BYTES);
    const int tid = threadIdx.x, warp = tid >> 5, lane = tid & 31;
    const int g = lane >> 2, t4 = lane & 3;
    const int wm = warp >> 1, wn = warp & 1;
    const int m0 = blockIdx.y * 128, n0 = blockIdx.x * 128, n8base = n0 >> 3;

    float acc[2][8][4];
    #pragma unroll
    for (int i = 0; i < 2; i++)
        #pragma unroll
        for (int j = 0; j < 8; j++)
            #pragma unroll
            for (int k = 0; k < 4; k++) acc[i][j][k] = 0.f;

    auto issue = [&](int ks, int s) {
        #pragma unroll
        for (int p = 0; p < 2; p++) {
            int id = p * 256 + tid;
            int row = id >> 2, c8 = id & 3;
            cp16(&sA[((size_t)s * 128 + row) * GA_STRIDE + c8 * 8],
                 A + (size_t)(m0 + row) * KDIM + ks * 32 + c8 * 8);
        }
        #pragma unroll
        for (int p = 0; p < 4; p++) {
            int id = p * 256 + tid;
            int plane = id >> 9, rem = id & 511;
            int n8l = rem >> 5, r32 = rem & 31;
            const f16* src = (plane ? Blo : Bhi)
                + ((size_t)(n8base + n8l) * 64 + ks * 2) * 128 + r32 * 8;
            cp16(&sB[((size_t)(s * 2 + plane) * 16 + n8l) * 256 + r32 * 8], src);
        }
    };

    issue(0, 0); cp_commit();
    for (int ks = 0; ks < KDIM / 32; ks++) {
        cp_wait<0>(); __syncthreads();
        if (ks + 1 < KDIM / 32) issue(ks + 1, (ks + 1) & 1);
        cp_commit();
        const int s = ks & 1;
        #pragma unroll
        for (int kk = 0; kk < 2; kk++) {
            const int kloc = kk * 16 + t4 * 2;
            uint32_t a[2][4];
            #pragma unroll
            for (int mf = 0; mf < 2; mf++) {
                int m = wm * 32 + mf * 16 + g;
                const f16* p0 = &sA[((size_t)s * 128 + m) * GA_STRIDE];
                a[mf][0] = *(const uint32_t*)(p0 + kloc);
                a[mf][1] = *(const uint32_t*)(p0 + 8 * GA_STRIDE + kloc);
                a[mf][2] = *(const uint32_t*)(p0 + kloc + 8);
                a[mf][3] = *(const uint32_t*)(p0 + 8 * GA_STRIDE + kloc + 8);
            }
            #pragma unroll
            for (int nf = 0; nf < 8; nf++) {
                size_t base = ((size_t)(s * 2) * 16 + wn * 8 + nf) * 256 + kk * 128 + lane * 4;
                uint2 bh = *(const uint2*)&sB[base];
                uint2 bl = *(const uint2*)&sB[base + 16 * 256];
                #pragma unroll
                for (int mf = 0; mf < 2; mf++) {
                    mma16f(acc[mf][nf], a[mf], bh);
                    mma16f(acc[mf][nf], a[mf], bl);
                }
            }
        }
    }
    #pragma unroll
    for (int mf = 0; mf < 2; mf++)
        #pragma unroll
        for (int nf = 0; nf < 8; nf++) {
            int col = n0 + (wn * 8 + nf) * 8 + 2 * t4;
            int r0  = m0 + wm * 32 + mf * 16 + g;
            float bv0 = bias[col], bv1 = bias[col + 1];
            C[(size_t)r0 * NGATE + col]           = acc[mf][nf][0] + bv0;
            C[(size_t)r0 * NGATE + col + 1]       = acc[mf][nf][1] + bv1;
            C[(size_t)(r0 + 8) * NGATE + col]     = acc[mf][nf][2] + bv0;
            C[(size_t)(r0 + 8) * NGATE + col + 1] = acc[mf][nf][3] + bv1;
        }
}

// ======================================================================
// Balanced step launch t (0..257), 128 CTAs x 256 thr.
// K-stage = 128 (8 tiles, 2-stage pipeline); lo-plane rec term on
// fp16-accum MMA (2x rate), folded into fp32 at the end.
// ======================================================================
#define SH_STRIDE 136                              // 128 k + 8 pad
#define A_BYTES (2 * 2 * 64 * SH_STRIDE * 2)       // 69632
#define B_STG (2 * B2_HALFS)                       // 20480 halfs per stage
#define S_SMEM (A_BYTES + 2 * B_STG * 2)           // + 81920 = 151552

__global__ __launch_bounds__(256, 1) void lstm_bal(
    int t, const float* __restrict__ Z0, const float* __restrict__ b1,
    f16* H1, f16* H2, const f16* __restrict__ hz,
    float* c0buf, float* c1buf, float* z1x,
    const f16* __restrict__ Wp0, const f16* __restrict__ Wp1, float* out)
{
    const bool isL1 = blockIdx.x >= 64;
    if (!isL1 && t == 257) return;
    if (isL1 && t == 0) return;
    const int cta = blockIdx.x & 63;

    extern __shared__ char smem[];
    f16* sA = (f16*)smem;                          // [slot2][stage2][64][136]
    f16* sB = (f16*)(smem + A_BYTES);              // [stage2][sub2][uu20][512]

    const int tid = threadIdx.x, warp = tid >> 5, lane = tid & 31;
    const int g = lane >> 2, t4 = lane & 3;
    const int mw = warp & 3, ng = warp >> 2;
    const int mrow = mw * 16 + g;

    const bool zact   = (t >= 1 && t <= 256);
    const bool recact = isL1 ? (t >= 2) : (t <= 255);
    const int  sidx   = isL1 ? (t - 2) : t;
    const f16* a0src  = isL1 ? ((t >= 3) ? H2 + (size_t)(t - 3) * HSTEP : hz)
                             : (zact ? H1 + (size_t)(t - 1) * HSTEP : hz);
    const f16* a1src  = zact ? H1 + (size_t)(t - 1) * HSTEP : hz;
    const f16* Wp = (isL1 ? Wp1 : Wp0) + (size_t)cta * (16 * (size_t)B2_HALFS);

    auto issue = [&](int tile, int st) {           // tile = 0..7 (128 k each)
        #pragma unroll
        for (int qq = 0; qq < 4; qq++) {           // A slot0: 1024 cp16
            int id = qq * 256 + tid;
            int row = id >> 4, c8 = id & 15;
            cp16(&sA[((size_t)st * 64 + row) * SH_STRIDE + c8 * 8],
                 a0src + (size_t)row * KDIM + tile * 128 + c8 * 8);
        }
        if (isL1) {
            #pragma unroll
            for (int qq = 0; qq < 4; qq++) {       // A slot1
                int id = qq * 256 + tid;
                int row = id >> 4, c8 = id & 15;
                cp16(&sA[((size_t)(2 + st) * 64 + row) * SH_STRIDE + c8 * 8],
                     a1src + (size_t)row * KDIM + tile * 128 + c8 * 8);
            }
        }
        #pragma unroll
        for (int qq = 0; qq < 10; qq++) {          // B: 2560 cp16 (two packed subtiles)
            int id = qq * 256 + tid;
            cp16(&sB[(size_t)st * B_STG + id * 8],
                 Wp + (size_t)tile * B_STG + id * 8);
        }
    };

    // ---- register prefetch of z-term and c-state ----
    const int n0r = cta * 16 + ng * 8;
    float zr[4][4], cold[4] = {0.f, 0.f, 0.f, 0.f};
    if (recact) {
        const float* zrd = isL1 ? (z1x + (size_t)(sidx & 1) * ZSTEP)
                                : (Z0 + (size_t)t * ZSTEP);
        #pragma unroll
        for (int gt = 0; gt < 4; gt++)
            #pragma unroll
            for (int rr = 0; rr < 2; rr++) {
                float2 v = __ldg((const float2*)(zrd + (size_t)(mrow + rr * 8) * NGATE
                                                 + gt * 1024 + n0r + t4 * 2));
                zr[gt][rr * 2] = v.x; zr[gt][rr * 2 + 1] = v.y;
            }
        if (sidx > 0) {
            const float* cb = isL1 ? c1buf : c0buf;
            #pragma unroll
            for (int rr = 0; rr < 2; rr++) {
                float2 cv = __ldg((const float2*)(cb + (size_t)(mrow + rr * 8) * KDIM
                                                  + n0r + t4 * 2));
                cold[rr * 2] = cv.x; cold[rr * 2 + 1] = cv.y;
            }
        }
    }

    float acc[6][4];
    #pragma unroll
    for (int i = 0; i < 6; i++)
        #pragma unroll
        for (int e = 0; e < 4; e++) acc[i][e] = 0.f;
    uint32_t accl[4][2];                           // fp16 accum for lo-plane rec
    #pragma unroll
    for (int i = 0; i < 4; i++) { accl[i][0] = 0u; accl[i][1] = 0u; }

    issue(0, 0); cp_commit();

    for (int tile = 0; tile < 8; tile++) {
        cp_wait<0>();
        __syncthreads();
        if (tile + 1 < 8) { issue(tile + 1, (tile + 1) & 1); cp_commit(); }
        const int st = tile & 1;
        const f16* A0 = &sA[(size_t)st * 64 * SH_STRIDE];
        const f16* A1 = isL1 ? &sA[(size_t)(2 + st) * 64 * SH_STRIDE] : A0;

        #pragma unroll
        for (int sub = 0; sub < 2; sub++) {
            const f16* B = &sB[(size_t)st * B_STG + (size_t)sub * B2_HALFS];
            #pragma unroll
            for (int kb = 0; kb < 4; kb++) {
                const int kloc = sub * 64 + kb * 16 + t4 * 2;
                uint32_t a0[4], a1[4];
                a0[0] = *(const uint32_t*)(A0 + (size_t)mrow * SH_STRIDE + kloc);
                a0[1] = *(const uint32_t*)(A0 + (size_t)(mrow + 8) * SH_STRIDE + kloc);
                a0[2] = *(const uint32_t*)(A0 + (size_t)mrow * SH_STRIDE + kloc + 8);
                a0[3] = *(const uint32_t*)(A0 + (size_t)(mrow + 8) * SH_STRIDE + kloc + 8);
                if (isL1) {
                    a1[0] = *(const uint32_t*)(A1 + (size_t)mrow * SH_STRIDE + kloc);
                    a1[1] = *(const uint32_t*)(A1 + (size_t)(mrow + 8) * SH_STRIDE + kloc);
                    a1[2] = *(const uint32_t*)(A1 + (size_t)mrow * SH_STRIDE + kloc + 8);
                    a1[3] = *(const uint32_t*)(A1 + (size_t)(mrow + 8) * SH_STRIDE + kloc + 8);
                } else {
                    a1[0] = a0[0]; a1[1] = a0[1]; a1[2] = a0[2]; a1[3] = a0[3];
                }
                #pragma unroll
                for (int gt = 0; gt < 4; gt++) {   // rec: hi fp32-acc, lo fp16-acc
                    int u = gt * 2 + ng;
                    uint2 bh = *(const uint2*)&B[(size_t)u * 512 + kb * 128 + lane * 4];
                    uint2 bl = *(const uint2*)&B[(size_t)(12 + u) * 512 + kb * 128 + lane * 4];
                    mma16f(acc[gt], a0, bh);
                    mma16h(accl[gt], a0, bl);
                }
                #pragma unroll
                for (int zz = 0; zz < 2; zz++) {   // z1x: 1-term fp32-acc
                    int u = 8 + ng * 2 + zz;
                    uint2 bh = *(const uint2*)&B[(size_t)u * 512 + kb * 128 + lane * 4];
                    mma16f(acc[4 + zz], a1, bh);
                }
            }
        }
    }

    // fold fp16 lo-accumulators into fp32
    #pragma unroll
    for (int gt = 0; gt < 4; gt++) {
        __half2 p0 = *(__half2*)&accl[gt][0];
        __half2 p1 = *(__half2*)&accl[gt][1];
        acc[gt][0] += __low2float(p0);  acc[gt][1] += __high2float(p0);
        acc[gt][2] += __low2float(p1);  acc[gt][3] += __high2float(p1);
    }

    // ---- rec epilogue ----
    if (recact) {
        float* cb = isL1 ? c1buf : c0buf;
        #pragma unroll
        for (int e = 0; e < 4; e++) {
            int row = mrow + (e >> 1) * 8;
            int col = n0r + t4 * 2 + (e & 1);
            float zi = acc[0][e] + zr[0][e];
            float zj = acc[1][e] + zr[1][e];
            float zf = acc[2][e] + zr[2][e];
            float zo = acc[3][e] + zr[3][e];
            float ig = 1.f / (1.f + expf(-zi));
            float fg = 1.f / (1.f + expf(-(zf + 1.f)));   // FORGET_BIAS = 1.0
            float og = 1.f / (1.f + expf(-zo));
            float cn = cold[e] * fg + ig * tanhf(zj);
            float hv = tanhf(cn) * og;
            cb[(size_t)row * KDIM + col] = cn;
            if (isL1) {
                out[(size_t)sidx * HSTEP + (size_t)row * KDIM + col] = hv;
                H2[(size_t)sidx * HSTEP + (size_t)row * KDIM + col] = __float2half(hv);
            } else {
                H1[(size_t)t * HSTEP + (size_t)row * KDIM + col] = __float2half(hv);
            }
        }
    }

    // ---- z1x epilogue ----
    if (zact) {
        const int s = t - 1;
        float* zw = z1x + (size_t)(s & 1) * ZSTEP;
        const int zbase = (isL1 ? 2048 : 0) + cta * 32 + ng * 16;
        #pragma unroll
        for (int zz = 0; zz < 2; zz++)
            #pragma unroll
            for (int e = 0; e < 4; e++) {
                int row = mrow + (e >> 1) * 8;
                int col = zbase + zz * 8 + t4 * 2 + (e & 1);
                zw[(size_t)row * NGATE + col] = acc[4 + zz][e] + __ldg(b1 + col);
            }
    }
}

// ======================================================================
extern "C" void kernel_launch(void* const* d_in, const int* in_sizes, int n_in,
                              void* d_out, int out_size)
{
    const float* X  = (const float*)d_in[0];
    const float* W0 = (const float*)d_in[1];
    const float* b0 = (const float*)d_in[2];
    const float* W1 = (const float*)d_in[3];
    const float* b1 = (const float*)d_in[4];
    float* out = (float*)d_out;

    float *Z0, *c0, *c1, *z1x;
    f16 *X16, *Wg0, *H1, *H2, *hz, *WpL0, *WpL1;
    cudaGetSymbolAddress((void**)&Z0,   g_Z0);
    cudaGetSymbolAddress((void**)&c0,   g_c0);
    cudaGetSymbolAddress((void**)&c1,   g_c1);
    cudaGetSymbolAddress((void**)&z1x,  g_z1x);
    cudaGetSymbolAddress((void**)&X16,  g_X16);
    cudaGetSymbolAddress((void**)&Wg0,  g_Wg0);
    cudaGetSymbolAddress((void**)&H1,   g_H1);
    cudaGetSymbolAddress((void**)&H2,   g_H2);
    cudaGetSymbolAddress((void**)&hz,   g_hz);
    cudaGetSymbolAddress((void**)&WpL0, g_WpL0);
    cudaGetSymbolAddress((void**)&WpL1, g_WpL1);

    const size_t WP0 = (size_t)KDIM * NGATE;
    const size_t NX  = (size_t)T_STEPS * HSTEP;

    cudaFuncSetAttribute(gemm_z0,  cudaFuncAttributeMaxDynamicSharedMemorySize, G_SMEM);
    cudaFuncSetAttribute(lstm_bal, cudaFuncAttributeMaxDynamicSharedMemorySize, S_SMEM);

    const int pb = 256;
    pack_gemmW<<<(int)((WP0 + pb - 1) / pb), pb>>>(W0, Wg0, Wg0 + WP0);
    pack_bal<<<(int)((WPACK + pb - 1) / pb), pb>>>(W0, W1, WpL0, 0);
    pack_bal<<<(int)((WPACK + pb - 1) / pb), pb>>>(W0, W1, WpL1, 1);
    cvt_f16<<<(int)((NX + 255) / 256), 256>>>(X, X16, NX);

    gemm_z0<<<dim3(NGATE / 128, (T_STEPS * BATCH) / 128), 256, G_SMEM>>>(
        X16, Wg0, Wg0 + WP0, b0, Z0);

    for (int t = 0; t <= 257; t++) {
        lstm_bal<<<128, 256, S_SMEM>>>(
            t, Z0, b1, H1, H2, hz, c0, c1, z1x, WpL0, WpL1, out);
    }
}

// round 15
// speedup vs baseline: 1.8049x; 1.0679x over previous
#include <cuda_runtime.h>
#include <cuda_fp16.h>
#include <cstdint>
#include <cmath>

#define T_STEPS 256
#define BATCH   64
#define KDIM    1024
#define NGATE   4096
#define HSTEP   ((size_t)BATCH * KDIM)
#define ZSTEP   ((size_t)BATCH * NGATE)

typedef __half f16;

// ---------------- scratch globals ----------------
__device__ float g_Z0[(size_t)T_STEPS * BATCH * NGATE];
__device__ f16   g_X16[(size_t)T_STEPS * BATCH * KDIM];
__device__ f16   g_Wg0[2][(size_t)KDIM * NGATE];        // Z0 W, fp16 hi/lo
__device__ f16   g_H1[(size_t)T_STEPS * BATCH * KDIM];
__device__ f16   g_H2[(size_t)T_STEPS * BATCH * KDIM];
__device__ f16   g_hz[BATCH * KDIM];                    // never written: zeros
__device__ float g_c0[BATCH * KDIM];
__device__ float g_c1[BATCH * KDIM];
__device__ float g_z1x[2][BATCH * NGATE];               // ping-pong, b1 included
// step W pack: per CTA [ktile16][uu20][kb4][128]
#define B2_HALFS 10240
#define WPACK ((size_t)64 * 16 * B2_HALFS)
__device__ f16   g_WpL0[WPACK];
__device__ f16   g_WpL1[WPACK];

#define DEVFN __device__ __forceinline__

DEVFN void mma16f(float* c, const uint32_t* a, uint2 b) {
    asm volatile("mma.sync.aligned.m16n8k16.row.col.f32.f16.f16.f32 "
        "{%0,%1,%2,%3},{%4,%5,%6,%7},{%8,%9},{%0,%1,%2,%3};"
        : "+f"(c[0]), "+f"(c[1]), "+f"(c[2]), "+f"(c[3])
        : "r"(a[0]), "r"(a[1]), "r"(a[2]), "r"(a[3]), "r"(b.x), "r"(b.y));
}
DEVFN void cp16(void* s, const void* g) {
    uint32_t sa = (uint32_t)__cvta_generic_to_shared(s);
    asm volatile("cp.async.cg.shared.global [%0], [%1], 16;" :: "r"(sa), "l"(g));
}
DEVFN void cp_commit() { asm volatile("cp.async.commit_group;"); }
template <int N> DEVFN void cp_wait() { asm volatile("cp.async.wait_group %0;" :: "n"(N)); }

// ======================================================================
// Packs (unchanged)
// ======================================================================
__global__ void pack_bal(const float* __restrict__ W0, const float* __restrict__ W1,
                         f16* __restrict__ dst, int grp)
{
    size_t idx = (size_t)blockIdx.x * blockDim.x + threadIdx.x;
    if (idx >= WPACK) return;
    int inner = (int)(idx & 127);
    int kb    = (int)((idx >> 7) & 3);
    size_t q  = idx >> 9;
    int uu    = (int)(q % 20); q /= 20;
    int tile  = (int)(q & 15); q >>= 4;
    int cta   = (int)q;
    int plane = (uu >= 12), u = plane ? (uu - 12) : uu;
    int lane = inner >> 2, reg = (inner >> 1) & 1, hh = inner & 1;
    int cc = lane >> 2, tg = lane & 3;
    int k = tile * 64 + kb * 16 + reg * 8 + tg * 2 + hh;
    int row, col; const float* src;
    if (u < 8) {
        int gt = u >> 1, hf = u & 1;
        col = gt * 1024 + cta * 16 + hf * 8 + cc;
        row = 1024 + k;
        src = grp ? W1 : W0;
    } else {
        col = (grp ? 2048 : 0) + cta * 32 + (u - 8) * 8 + cc;
        row = k;
        src = W1;
    }
    float w = src[(size_t)row * NGATE + col];
    f16 hi = __float2half(w);
    dst[idx] = plane ? __float2half(w - __half2float(hi)) : hi;
}

__global__ void pack_gemmW(const float* __restrict__ W, f16* __restrict__ hi,
                           f16* __restrict__ lo)
{
    size_t idx = (size_t)blockIdx.x * blockDim.x + threadIdx.x;
    if (idx >= (size_t)KDIM * NGATE) return;
    int k = (int)(idx >> 12), col = (int)(idx & 4095);
    int n8 = col >> 3, cc = col & 7;
    int kb = k >> 4, kl = k & 15;
    int reg = kl >> 3, tg = (kl >> 1) & 3, hh = kl & 1;
    int lane = cc * 4 + tg;
    size_t dst = ((size_t)n8 * 64 + kb) * 128 + lane * 4 + reg * 2 + hh;
    float w = W[idx];
    f16 h = __float2half(w);
    hi[dst] = h;
    lo[dst] = __float2half(w - __half2float(h));
}

__global__ void cvt_f16(const float* __restrict__ A, f16* __restrict__ B, size_t n)
{
    size_t idx = (size_t)blockIdx.x * blockDim.x + threadIdx.x;
    if (idx < n) B[idx] = __float2half(A[idx]);
}

// ======================================================================
// Z0 pre-GEMM (unchanged from R14)
// ======================================================================
#define GA_STRIDE 40
#define G_SA_BYTES (2 * 128 * GA_STRIDE * 2)
#define G_SMEM (G_SA_BYTES + 2 * 2 * 16 * 256 * 2)

__global__ __launch_bounds__(256) void gemm_z0(
    const f16* __restrict__ A, const f16* __restrict__ Bhi, const f16* __restrict__ Blo,
    const float* __restrict__ bias, float* __restrict__ C)
{
    extern __shared__ char smem[];
    f16* sA = (f16*)smem;
    f16* sB = (f16*)(smem + G_SA_BYTES);
    const int tid = threadIdx.x, warp = tid >> 5, lane = tid & 31;
    const int g = lane >> 2, t4 = lane & 3;
    const int wm = warp >> 1, wn = warp & 1;
    const int m0 = blockIdx.y * 128, n0 = blockIdx.x * 128, n8base = n0 >> 3;

    float acc[2][8][4];
    #pragma unroll
    for (int i = 0; i < 2; i++)
        #pragma unroll
        for (int j = 0; j < 8; j++)
            #pragma unroll
            for (int k = 0; k < 4; k++) acc[i][j][k] = 0.f;

    auto issue = [&](int ks, int s) {
        #pragma unroll
        for (int p = 0; p < 2; p++) {
            int id = p * 256 + tid;
            int row = id >> 2, c8 = id & 3;
            cp16(&sA[((size_t)s * 128 + row) * GA_STRIDE + c8 * 8],
                 A + (size_t)(m0 + row) * KDIM + ks * 32 + c8 * 8);
        }
        #pragma unroll
        for (int p = 0; p < 4; p++) {
            int id = p * 256 + tid;
            int plane = id >> 9, rem = id & 511;
            int n8l = rem >> 5, r32 = rem & 31;
            const f16* src = (plane ? Blo : Bhi)
                + ((size_t)(n8base + n8l) * 64 + ks * 2) * 128 + r32 * 8;
            cp16(&sB[((size_t)(s * 2 + plane) * 16 + n8l) * 256 + r32 * 8], src);
        }
    };

    issue(0, 0); cp_commit();
    for (int ks = 0; ks < KDIM / 32; ks++) {
        cp_wait<0>(); __syncthreads();
        if (ks + 1 < KDIM / 32) issue(ks + 1, (ks + 1) & 1);
        cp_commit();
        const int s = ks & 1;
        #pragma unroll
        for (int kk = 0; kk < 2; kk++) {
            const int kloc = kk * 16 + t4 * 2;
            uint32_t a[2][4];
            #pragma unroll
            for (int mf = 0; mf < 2; mf++) {
                int m = wm * 32 + mf * 16 + g;
                const f16* p0 = &sA[((size_t)s * 128 + m) * GA_STRIDE];
                a[mf][0] = *(const uint32_t*)(p0 + kloc);
                a[mf][1] = *(const uint32_t*)(p0 + 8 * GA_STRIDE + kloc);
                a[mf][2] = *(const uint32_t*)(p0 + kloc + 8);
                a[mf][3] = *(const uint32_t*)(p0 + 8 * GA_STRIDE + kloc + 8);
            }
            #pragma unroll
            for (int nf = 0; nf < 8; nf++) {
                size_t base = ((size_t)(s * 2) * 16 + wn * 8 + nf) * 256 + kk * 128 + lane * 4;
                uint2 bh = *(const uint2*)&sB[base];
                uint2 bl = *(const uint2*)&sB[base + 16 * 256];
                #pragma unroll
                for (int mf = 0; mf < 2; mf++) {
                    mma16f(acc[mf][nf], a[mf], bh);
                    mma16f(acc[mf][nf], a[mf], bl);
                }
            }
        }
    }
    #pragma unroll
    for (int mf = 0; mf < 2; mf++)
        #pragma unroll
        for (int nf = 0; nf < 8; nf++) {
            int col = n0 + (wn * 8 + nf) * 8 + 2 * t4;
            int r0  = m0 + wm * 32 + mf * 16 + g;
            float bv0 = bias[col], bv1 = bias[col + 1];
            C[(size_t)r0 * NGATE + col]           = acc[mf][nf][0] + bv0;
            C[(size_t)r0 * NGATE + col + 1]       = acc[mf][nf][1] + bv1;
            C[(size_t)(r0 + 8) * NGATE + col]     = acc[mf][nf][2] + bv0;
            C[(size_t)(r0 + 8) * NGATE + col + 1] = acc[mf][nf][3] + bv1;
        }
}

// ======================================================================
// Balanced step launch t (0..257), 128 CTAs x 256 thr, K-stage 128.
// R15: PDL — stage-0 W loads issued BEFORE cudaGridDependencySynchronize
// (no cross-launch dep); trigger fires after the MMA loop so the next
// launch's W-fill overlaps our epilogue + drain.
// ======================================================================
#define SH_STRIDE 136
#define A_BYTES (2 * 2 * 64 * SH_STRIDE * 2)       // 69632
#define B_STG (2 * B2_HALFS)                       // 20480 halfs per stage
#define S_SMEM (A_BYTES + 2 * B_STG * 2)           // 151552

__global__ __launch_bounds__(256, 1) void lstm_bal(
    int t, const float* __restrict__ Z0, const float* __restrict__ b1,
    f16* H1, f16* H2, const f16* __restrict__ hz,
    float* c0buf, float* c1buf, float* z1x,
    const f16* __restrict__ Wp0, const f16* __restrict__ Wp1, float* out)
{
    const bool isL1 = blockIdx.x >= 64;
    if (!isL1 && t == 257) { cudaGridDependencySynchronize(); return; }
    if (isL1 && t == 0)    { cudaGridDependencySynchronize(); return; }
    const int cta = blockIdx.x & 63;

    extern __shared__ char smem[];
    f16* sA = (f16*)smem;                          // [slot2][stage2][64][136]
    f16* sB = (f16*)(smem + A_BYTES);              // [stage2][sub2][uu20][512]

    const int tid = threadIdx.x, warp = tid >> 5, lane = tid & 31;
    const int g = lane >> 2, t4 = lane & 3;
    const int mw = warp & 3, ng = warp >> 2;
    const int mrow = mw * 16 + g;

    const bool zact   = (t >= 1 && t <= 256);
    const bool recact = isL1 ? (t >= 2) : (t <= 255);
    const int  sidx   = isL1 ? (t - 2) : t;
    const f16* Wp = (isL1 ? Wp1 : Wp0) + (size_t)cta * (16 * (size_t)B2_HALFS);

    auto issueW = [&](int tile, int st) {
        #pragma unroll
        for (int qq = 0; qq < 10; qq++) {
            int id = qq * 256 + tid;
            cp16(&sB[(size_t)st * B_STG + id * 8],
                 Wp + (size_t)tile * B_STG + id * 8);
        }
    };

    // ---- pre-sync: stage-0 weights (no dependency on prior launch) ----
    issueW(0, 0); cp_commit();

    cudaGridDependencySynchronize();

    // ---- post-sync: h sources, z/c prefetch, stage-0 A ----
    const f16* a0src  = isL1 ? ((t >= 3) ? H2 + (size_t)(t - 3) * HSTEP : hz)
                             : (zact ? H1 + (size_t)(t - 1) * HSTEP : hz);
    const f16* a1src  = zact ? H1 + (size_t)(t - 1) * HSTEP : hz;

    auto issueA = [&](int tile, int st) {
        #pragma unroll
        for (int qq = 0; qq < 4; qq++) {
            int id = qq * 256 + tid;
            int row = id >> 4, c8 = id & 15;
            cp16(&sA[((size_t)st * 64 + row) * SH_STRIDE + c8 * 8],
                 a0src + (size_t)row * KDIM + tile * 128 + c8 * 8);
        }
        if (isL1) {
            #pragma unroll
            for (int qq = 0; qq < 4; qq++) {
                int id = qq * 256 + tid;
                int row = id >> 4, c8 = id & 15;
                cp16(&sA[((size_t)(2 + st) * 64 + row) * SH_STRIDE + c8 * 8],
                     a1src + (size_t)row * KDIM + tile * 128 + c8 * 8);
            }
        }
    };

    issueA(0, 0); cp_commit();

    const int n0r = cta * 16 + ng * 8;
    float zr[4][4], cold[4] = {0.f, 0.f, 0.f, 0.f};
    if (recact) {
        const float* zrd = isL1 ? (z1x + (size_t)(sidx & 1) * ZSTEP)
                                : (Z0 + (size_t)t * ZSTEP);
        #pragma unroll
        for (int gt = 0; gt < 4; gt++)
            #pragma unroll
            for (int rr = 0; rr < 2; rr++) {
                float2 v = __ldg((const float2*)(zrd + (size_t)(mrow + rr * 8) * NGATE
                                                 + gt * 1024 + n0r + t4 * 2));
                zr[gt][rr * 2] = v.x; zr[gt][rr * 2 + 1] = v.y;
            }
        if (sidx > 0) {
            const float* cb = isL1 ? c1buf : c0buf;
            #pragma unroll
            for (int rr = 0; rr < 2; rr++) {
                float2 cv = __ldg((const float2*)(cb + (size_t)(mrow + rr * 8) * KDIM
                                                  + n0r + t4 * 2));
                cold[rr * 2] = cv.x; cold[rr * 2 + 1] = cv.y;
            }
        }
    }

    float acc[6][4];
    #pragma unroll
    for (int i = 0; i < 6; i++)
        #pragma unroll
        for (int e = 0; e < 4; e++) acc[i][e] = 0.f;

    for (int tile = 0; tile < 8; tile++) {
        cp_wait<0>();
        __syncthreads();
        if (tile + 1 < 8) {
            const int st1 = (tile + 1) & 1;
            issueW(tile + 1, st1);
            issueA(tile + 1, st1);
            cp_commit();
        }
        const int st = tile & 1;
        const f16* A0 = &sA[(size_t)st * 64 * SH_STRIDE];
        const f16* A1 = isL1 ? &sA[(size_t)(2 + st) * 64 * SH_STRIDE] : A0;

        #pragma unroll
        for (int sub = 0; sub < 2; sub++) {
            const f16* B = &sB[(size_t)st * B_STG + (size_t)sub * B2_HALFS];
            #pragma unroll
            for (int kb = 0; kb < 4; kb++) {
                const int kloc = sub * 64 + kb * 16 + t4 * 2;
                uint32_t a0[4], a1[4];
                a0[0] = *(const uint32_t*)(A0 + (size_t)mrow * SH_STRIDE + kloc);
                a0[1] = *(const uint32_t*)(A0 + (size_t)(mrow + 8) * SH_STRIDE + kloc);
                a0[2] = *(const uint32_t*)(A0 + (size_t)mrow * SH_STRIDE + kloc + 8);
                a0[3] = *(const uint32_t*)(A0 + (size_t)(mrow + 8) * SH_STRIDE + kloc + 8);
                if (isL1) {
                    a1[0] = *(const uint32_t*)(A1 + (size_t)mrow * SH_STRIDE + kloc);
                    a1[1] = *(const uint32_t*)(A1 + (size_t)(mrow + 8) * SH_STRIDE + kloc);
                    a1[2] = *(const uint32_t*)(A1 + (size_t)mrow * SH_STRIDE + kloc + 8);
                    a1[3] = *(const uint32_t*)(A1 + (size_t)(mrow + 8) * SH_STRIDE + kloc + 8);
                } else {
                    a1[0] = a0[0]; a1[1] = a0[1]; a1[2] = a0[2]; a1[3] = a0[3];
                }
                #pragma unroll
                for (int gt = 0; gt < 4; gt++) {   // rec: 2-term fp32-acc
                    int u = gt * 2 + ng;
                    uint2 bh = *(const uint2*)&B[(size_t)u * 512 + kb * 128 + lane * 4];
                    uint2 bl = *(const uint2*)&B[(size_t)(12 + u) * 512 + kb * 128 + lane * 4];
                    mma16f(acc[gt], a0, bh);
                    mma16f(acc[gt], a0, bl);
                }
                #pragma unroll
                for (int zz = 0; zz < 2; zz++) {   // z1x: 1-term
                    int u = 8 + ng * 2 + zz;
                    uint2 bh = *(const uint2*)&B[(size_t)u * 512 + kb * 128 + lane * 4];
                    mma16f(acc[4 + zz], a1, bh);
                }
            }
        }
    }

    // allow the next launch to start its weight fill during our epilogue
    cudaTriggerProgrammaticLaunchCompletion();

    // ---- rec epilogue ----
    if (recact) {
        float* cb = isL1 ? c1buf : c0buf;
        #pragma unroll
        for (int e = 0; e < 4; e++) {
            int row = mrow + (e >> 1) * 8;
            int col = n0r + t4 * 2 + (e & 1);
            float zi = acc[0][e] + zr[0][e];
            float zj = acc[1][e] + zr[1][e];
            float zf = acc[2][e] + zr[2][e];
            float zo = acc[3][e] + zr[3][e];
            float ig = 1.f / (1.f + expf(-zi));
            float fg = 1.f / (1.f + expf(-(zf + 1.f)));   // FORGET_BIAS = 1.0
            float og = 1.f / (1.f + expf(-zo));
            float cn = cold[e] * fg + ig * tanhf(zj);
            float hv = tanhf(cn) * og;
            cb[(size_t)row * KDIM + col] = cn;
            if (isL1) {
                out[(size_t)sidx * HSTEP + (size_t)row * KDIM + col] = hv;
                H2[(size_t)sidx * HSTEP + (size_t)row * KDIM + col] = __float2half(hv);
            } else {
                H1[(size_t)t * HSTEP + (size_t)row * KDIM + col] = __float2half(hv);
            }
        }
    }

    // ---- z1x epilogue ----
    if (zact) {
        const int s = t - 1;
        float* zw = z1x + (size_t)(s & 1) * ZSTEP;
        const int zbase = (isL1 ? 2048 : 0) + cta * 32 + ng * 16;
        #pragma unroll
        for (int zz = 0; zz < 2; zz++)
            #pragma unroll
            for (int e = 0; e < 4; e++) {
                int row = mrow + (e >> 1) * 8;
                int col = zbase + zz * 8 + t4 * 2 + (e & 1);
                zw[(size_t)row * NGATE + col] = acc[4 + zz][e] + __ldg(b1 + col);
            }
    }
}

// ======================================================================
extern "C" void kernel_launch(void* const* d_in, const int* in_sizes, int n_in,
                              void* d_out, int out_size)
{
    const float* X  = (const float*)d_in[0];
    const float* W0 = (const float*)d_in[1];
    const float* b0 = (const float*)d_in[2];
    const float* W1 = (const float*)d_in[3];
    const float* b1 = (const float*)d_in[4];
    float* out = (float*)d_out;

    float *Z0, *c0, *c1, *z1x;
    f16 *X16, *Wg0, *H1, *H2, *hz, *WpL0, *WpL1;
    cudaGetSymbolAddress((void**)&Z0,   g_Z0);
    cudaGetSymbolAddress((void**)&c0,   g_c0);
    cudaGetSymbolAddress((void**)&c1,   g_c1);
    cudaGetSymbolAddress((void**)&z1x,  g_z1x);
    cudaGetSymbolAddress((void**)&X16,  g_X16);
    cudaGetSymbolAddress((void**)&Wg0,  g_Wg0);
    cudaGetSymbolAddress((void**)&H1,   g_H1);
    cudaGetSymbolAddress((void**)&H2,   g_H2);
    cudaGetSymbolAddress((void**)&hz,   g_hz);
    cudaGetSymbolAddress((void**)&WpL0, g_WpL0);
    cudaGetSymbolAddress((void**)&WpL1, g_WpL1);

    const size_t WP0 = (size_t)KDIM * NGATE;
    const size_t NX  = (size_t)T_STEPS * HSTEP;

    cudaFuncSetAttribute(gemm_z0,  cudaFuncAttributeMaxDynamicSharedMemorySize, G_SMEM);
    cudaFuncSetAttribute(lstm_bal, cudaFuncAttributeMaxDynamicSharedMemorySize, S_SMEM);

    const int pb = 256;
    pack_gemmW<<<(int)((WP0 + pb - 1) / pb), pb>>>(W0, Wg0, Wg0 + WP0);
    pack_bal<<<(int)((WPACK + pb - 1) / pb), pb>>>(W0, W1, WpL0, 0);
    pack_bal<<<(int)((WPACK + pb - 1) / pb), pb>>>(W0, W1, WpL1, 1);
    cvt_f16<<<(int)((NX + 255) / 256), 256>>>(X, X16, NX);

    gemm_z0<<<dim3(NGATE / 128, (T_STEPS * BATCH) / 128), 256, G_SMEM>>>(
        X16, Wg0, Wg0 + WP0, b0, Z0);

    // ---- fused recurrence with PDL between step launches ----
    cudaLaunchAttribute attrs[1];
    attrs[0].id = cudaLaunchAttributeProgrammaticStreamSerialization;
    attrs[0].val.programmaticStreamSerializationAllowed = 1;

    cudaLaunchConfig_t cfg = {};
    cfg.gridDim  = dim3(128, 1, 1);
    cfg.blockDim = dim3(256, 1, 1);
    cfg.dynamicSmemBytes = S_SMEM;
    cfg.stream = 0;
    cfg.attrs = attrs;
    cfg.numAttrs = 1;

    for (int t = 0; t <= 257; t++) {
        cudaLaunchKernelEx(&cfg, lstm_bal,
            t, (const float*)Z0, b1, H1, H2, (const f16*)hz,
            c0, c1, z1x, (const f16*)WpL0, (const f16*)WpL1, out);
    }
}